// round 7
// baseline (speedup 1.0000x reference)
#include <cuda_runtime.h>
#include <cstdint>

#define NLEV   3
#define KCODES 512
#define DIM    1024
#define NTOK   65536           // 16 * 4096
#define DECAY  0.99f
#define OMD    0.01f
#define EPSV   1e-5f

typedef unsigned long long ull;

// ---- scratch (__device__ globals: the sanctioned no-alloc path) ----
static __device__ __align__(16) float g_residual[(size_t)NTOK * DIM];  // 268 MB
static __device__ __align__(16) float g_sums[NLEV * KCODES * DIM];     // 6 MB
static __device__ float  g_counts[NLEV * KCODES];
static __device__ float  g_c2[NLEV * KCODES];
static __device__ float  g_cs[NLEV * KCODES];
static __device__ float  g_n[NLEV];
static __device__ double g_loss_acc[NLEV];
static __device__ int    g_idx[NTOK];

// packed fp32x2 FMA: c.lo += a.lo*b.lo ; c.hi += a.hi*b.hi  (exact fp32 per lane)
__device__ __forceinline__ void ffma2(ull& c, ull a, ull b) {
    asm("fma.rn.f32x2 %0, %1, %2, %0;" : "+l"(c) : "l"(a), "l"(b));
}
// vectorized float4 reduction to global
__device__ __forceinline__ void red4(float* p, float4 v) {
    asm volatile("red.global.add.v4.f32 [%0], {%1,%2,%3,%4};"
                 :: "l"(p), "f"(v.x), "f"(v.y), "f"(v.z), "f"(v.w) : "memory");
}

union U4 { float4 f; ull u[2]; };
union U2 { ull u; float f[2]; };

// ---------------------------------------------------------------- zero scratch
__global__ void k_zero() {
    int i = blockIdx.x * blockDim.x + threadIdx.x;
    if (i < NLEV * KCODES * DIM) g_sums[i] = 0.f;
    if (i < NLEV * KCODES)       g_counts[i] = 0.f;
    if (i < NLEV)                g_loss_acc[i] = 0.0;
}

// ---------------------------------------------------------------- ||C_k||^2
__global__ void k_c2(const float* __restrict__ codebooks) {
    int w    = (blockIdx.x * blockDim.x + threadIdx.x) >> 5;
    int lane = threadIdx.x & 31;
    if (w >= NLEV * KCODES) return;
    const float* row = codebooks + (size_t)w * DIM;
    float s = 0.f;
#pragma unroll
    for (int it = 0; it < DIM / 128; it++) {
        float4 v = *(const float4*)(row + lane * 4 + it * 128);
        s += v.x * v.x + v.y * v.y + v.z * v.z + v.w * v.w;
    }
#pragma unroll
    for (int o = 16; o; o >>= 1) s += __shfl_xor_sync(0xffffffffu, s, o);
    if (lane == 0) g_c2[w] = s;
}

// ---------------------------------------------------------------- assign (argmin)
// Block tile: 64 tokens x 128 codes; 256 threads; per-thread 4 tok x 8 codes,
// f32x2-packed accumulators over d-pairs. Single smem buffer, 2 barriers per
// 32-d chunk (the proven R2 structure), but with float4 STS staging (R5 layout):
// 6 x STS.128 per thread per chunk instead of 24 scalar STS.
// Score = ||C||^2 - 2*dot (per-token ||r||^2 constant -> same argmin).
#define ST_STRIDE (64 * 4 + 4)     // 260 floats per d-quad row
#define SC_STRIDE (128 * 4 + 4)    // 516 floats per d-quad row
#define ST_BUF (8 * ST_STRIDE)     // 2080 floats
#define SC_BUF (8 * SC_STRIDE)     // 4128 floats
#define SMEM_FLOATS (ST_BUF + SC_BUF)   // 6208 floats = 24832 B

__global__ void __launch_bounds__(256, 2) k_assign(int level,
                                                   const float* __restrict__ z_e,
                                                   const float* __restrict__ codebooks,
                                                   float* __restrict__ out_idx) {
    const float* resid = level ? g_residual : z_e;
    const float* cb    = codebooks + (size_t)level * KCODES * DIM;
    const float* c2p   = g_c2 + level * KCODES;
    const int t0 = blockIdx.x * 64;

    __shared__ float sT[ST_BUF];
    __shared__ float sC[SC_BUF];

    const int tid = threadIdx.x;
    const int tx = tid & 15;               // code lane
    const int ty = tid >> 4;               // token group
    const int ldrow = tid >> 3, lddq = tid & 7;  // staging decomposition

    float cmin[4];
    int   cidx[4];
#pragma unroll
    for (int i = 0; i < 4; i++) { cmin[i] = 3.4e38f; cidx[i] = 0; }

    for (int ct = 0; ct < 4; ct++) {                 // 4 code tiles of 128
        ull acc[4][8];
#pragma unroll
        for (int i = 0; i < 4; i++)
#pragma unroll
            for (int j = 0; j < 8; j++) acc[i][j] = 0ull;

        for (int dc = 0; dc < 32; dc++) {            // 32 D-chunks of 32
            __syncthreads();                         // previous chunk's reads done
            // stage T: 2 float4 per thread (coalesced, 8 threads/row-chunk)
#pragma unroll
            for (int i = 0; i < 2; i++) {
                int tok = ldrow + i * 32;
                float4 v = *(const float4*)(resid + (size_t)(t0 + tok) * DIM + dc * 32 + lddq * 4);
                *(float4*)&sT[lddq * ST_STRIDE + tok * 4] = v;
            }
            // stage C: 4 float4 per thread
#pragma unroll
            for (int i = 0; i < 4; i++) {
                int code = ldrow + i * 32;
                float4 v = *(const float4*)(cb + (size_t)(ct * 128 + code) * DIM + dc * 32 + lddq * 4);
                *(float4*)&sC[lddq * SC_STRIDE + code * 4] = v;
            }
            __syncthreads();                         // staging visible

#pragma unroll
            for (int dq = 0; dq < 8; dq++) {
                U4 A[4];
#pragma unroll
                for (int i = 0; i < 4; i++)
                    A[i].f = *(const float4*)&sT[dq * ST_STRIDE + (ty * 4 + i) * 4];
#pragma unroll
                for (int j = 0; j < 8; j++) {
                    U4 B;
                    B.f = *(const float4*)&sC[dq * SC_STRIDE + (j * 16 + tx) * 4];
#pragma unroll
                    for (int i = 0; i < 4; i++) {
                        ffma2(acc[i][j], A[i].u[0], B.u[0]);
                        ffma2(acc[i][j], A[i].u[1], B.u[1]);
                    }
                }
            }
        }

        // epilogue: scores + running argmin (lowest-index tie-break like jnp.argmin)
#pragma unroll
        for (int i = 0; i < 4; i++) {
            float mv = 3.4e38f; int mi = 0;
#pragma unroll
            for (int j = 0; j < 8; j++) {
                U2 a; a.u = acc[i][j];
                float dot = a.f[0] + a.f[1];
                int id = ct * 128 + j * 16 + tx;
                float sc = __ldg(c2p + id) - 2.f * dot;
                if (sc < mv) { mv = sc; mi = id; }
            }
#pragma unroll
            for (int off = 8; off; off >>= 1) {      // butterfly within 16 tx lanes
                float ov = __shfl_xor_sync(0xffffffffu, mv, off);
                int   oi = __shfl_xor_sync(0xffffffffu, mi, off);
                if (ov < mv || (ov == mv && oi < mi)) { mv = ov; mi = oi; }
            }
            if (mv < cmin[i]) { cmin[i] = mv; cidx[i] = mi; }
        }
    }

    if (tx == 0) {
#pragma unroll
        for (int i = 0; i < 4; i++) {
            int tok = t0 + 4 * ty + i;
            g_idx[tok] = cidx[i];
            out_idx[(size_t)level * NTOK + tok] = (float)cidx[i];
        }
    }
}

// ---------------------------------------------------------------- update
// 4 tokens/block; 64 threads/token, 16 floats/thread; red.v4 scatter.
__global__ void __launch_bounds__(256) k_update(int level,
                                                const float* __restrict__ z_e,
                                                const float* __restrict__ codebooks,
                                                float* __restrict__ out_zq) {
    const int tid = threadIdx.x;
    const int tok = blockIdx.x * 4 + (tid >> 6);
    const int d   = (tid & 63) * 16;
    const float* rin = level ? g_residual : z_e;
    const int idx = g_idx[tok];
    const float* q = codebooks + ((size_t)level * KCODES + idx) * DIM + d;
    const float* r = rin + (size_t)tok * DIM + d;
    float* sums = g_sums + ((size_t)level * KCODES + idx) * DIM + d;
    float* rout = g_residual + (size_t)tok * DIM + d;
    float* zo   = out_zq + (size_t)tok * DIM + d;

    float ls = 0.f;
#pragma unroll
    for (int v = 0; v < 4; v++) {
        float4 rv = *(const float4*)(r + v * 4);
        float4 qv = *(const float4*)(q + v * 4);
        float4 rq = make_float4(rv.x - qv.x, rv.y - qv.y, rv.z - qv.z, rv.w - qv.w);
        *(float4*)(rout + v * 4) = rq;
        if (level) {
            float4 z = *(const float4*)(zo + v * 4);
            z.x += qv.x; z.y += qv.y; z.z += qv.z; z.w += qv.w;
            *(float4*)(zo + v * 4) = z;
        } else {
            *(float4*)(zo + v * 4) = qv;
        }
        red4(sums + v * 4, rv);
        ls += rq.x * rq.x + rq.y * rq.y + rq.z * rq.z + rq.w * rq.w;
    }
    if ((tid & 63) == 0) atomicAdd(g_counts + level * KCODES + idx, 1.0f);

    // block loss reduction -> one double atomic
#pragma unroll
    for (int o = 16; o; o >>= 1) ls += __shfl_xor_sync(0xffffffffu, ls, o);
    __shared__ float red[8];
    const int warp = tid >> 5, lane = tid & 31;
    if (lane == 0) red[warp] = ls;
    __syncthreads();
    if (tid < 8) {
        float v = red[tid];
#pragma unroll
        for (int o = 4; o; o >>= 1) v += __shfl_xor_sync(0xffu, v, o);
        if (tid == 0) atomicAdd(&g_loss_acc[level], (double)v);
    }
}

// ---------------------------------------------------------------- cs + n
__global__ void k_csn(const float* __restrict__ ema_cluster) {
    const int l = blockIdx.x;
    const int k = threadIdx.x;   // 512 threads
    float cs = DECAY * ema_cluster[l * KCODES + k] + OMD * g_counts[l * KCODES + k];
    g_cs[l * KCODES + k] = cs;
    float s = cs;
#pragma unroll
    for (int o = 16; o; o >>= 1) s += __shfl_xor_sync(0xffffffffu, s, o);
    __shared__ float red[16];
    const int warp = threadIdx.x >> 5, lane = threadIdx.x & 31;
    if (lane == 0) red[warp] = s;
    __syncthreads();
    if (threadIdx.x < 16) {
        float v = red[threadIdx.x];
#pragma unroll
        for (int o = 8; o; o >>= 1) v += __shfl_xor_sync(0xffffu, v, o);
        if (threadIdx.x == 0) g_n[l] = v;
    }
}

// ---------------------------------------------------------------- new codebooks + loss
__global__ void k_cb(const float* __restrict__ ema_w,
                     float* __restrict__ out_cb,
                     float* __restrict__ out_loss) {
    const int i = blockIdx.x * blockDim.x + threadIdx.x;
    if (i == 0) {
        double L = (0.25 * g_loss_acc[0] + 0.5 * g_loss_acc[1] + 1.0 * g_loss_acc[2])
                   * (1.0 / ((double)NTOK * (double)DIM));
        *out_loss = (float)L;
    }
    if (i >= NLEV * KCODES * DIM) return;
    const int row = i >> 10;   // / DIM
    const int l   = row >> 9;  // / KCODES
    float w  = DECAY * ema_w[i] + OMD * g_sums[i];
    float cs = g_cs[row];
    float n  = g_n[l];
    float csn = (cs + EPSV) / (n + 0.00512f) * n;   // K*EPS = 512e-5
    out_cb[i] = w / csn;
}

// ---------------------------------------------------------------- launch
extern "C" void kernel_launch(void* const* d_in, const int* in_sizes, int n_in,
                              void* d_out, int out_size) {
    const float* z_e         = (const float*)d_in[0];
    const float* codebooks   = (const float*)d_in[1];
    const float* ema_cluster = (const float*)d_in[2];
    const float* ema_w       = (const float*)d_in[3];
    float* out = (float*)d_out;

    const size_t ZQ = (size_t)NTOK * DIM;
    float* out_zq   = out;
    float* out_loss = out + ZQ;
    float* out_idx  = out + ZQ + 1;
    float* out_cb   = out + ZQ + 1 + (size_t)NLEV * NTOK;

    k_zero<<<(NLEV * KCODES * DIM + 255) / 256, 256>>>();
    k_c2<<<(NLEV * KCODES * 32 + 255) / 256, 256>>>(codebooks);
    for (int l = 0; l < NLEV; l++) {
        k_assign<<<NTOK / 64, 256>>>(l, z_e, codebooks, out_idx);
        k_update<<<NTOK / 4, 256>>>(l, z_e, codebooks, out_zq);
    }
    k_csn<<<NLEV, 512>>>(ema_cluster);
    k_cb<<<(NLEV * KCODES * DIM + 255) / 256, 256>>>(ema_w, out_cb, out_loss);
}

// round 8
// speedup vs baseline: 2.3760x; 2.3760x over previous
#include <cuda_runtime.h>
#include <cuda_fp16.h>
#include <cstdint>

#define NLEV   3
#define KCODES 512
#define DIM    1024
#define NTOK   65536           // 16 * 4096
#define DECAY  0.99f
#define OMD    0.01f
#define EPSV   1e-5f

typedef unsigned long long ull;
typedef unsigned int       u32;
typedef unsigned short     u16;

// ---- scratch (__device__ globals: the sanctioned no-alloc path) ----
static __device__ __align__(16) float g_residual[(size_t)NTOK * DIM];  // 268 MB
static __device__ __align__(16) u16   g_ah[(size_t)NTOK * DIM];        // 134 MB fp16 hi
static __device__ __align__(16) u16   g_al[(size_t)NTOK * DIM];        // 134 MB fp16 lo
static __device__ __align__(16) u16   g_cbh[NLEV * KCODES * DIM];
static __device__ __align__(16) u16   g_cbl[NLEV * KCODES * DIM];
static __device__ __align__(16) float g_sums[NLEV * KCODES * DIM];
static __device__ float  g_counts[NLEV * KCODES];
static __device__ float  g_c2[NLEV * KCODES];
static __device__ float  g_cs[NLEV * KCODES];
static __device__ float  g_n[NLEV];
static __device__ double g_loss_acc[NLEV];
static __device__ int    g_idx[NTOK];

__device__ __forceinline__ u32 smem_u32(const void* p) {
    u32 a;
    asm("{ .reg .u64 t; cvta.to.shared.u64 t, %1; cvt.u32.u64 %0, t; }" : "=r"(a) : "l"(p));
    return a;
}
__device__ __forceinline__ void red4(float* p, float4 v) {
    asm volatile("red.global.add.v4.f32 [%0], {%1,%2,%3,%4};"
                 :: "l"(p), "f"(v.x), "f"(v.y), "f"(v.z), "f"(v.w) : "memory");
}
__device__ __forceinline__ void ldsm4(u32& r0, u32& r1, u32& r2, u32& r3, u32 addr) {
    asm volatile("ldmatrix.sync.aligned.m8n8.x4.shared.b16 {%0,%1,%2,%3}, [%4];"
                 : "=r"(r0), "=r"(r1), "=r"(r2), "=r"(r3) : "r"(addr));
}
__device__ __forceinline__ void ldsm2(u32& r0, u32& r1, u32 addr) {
    asm volatile("ldmatrix.sync.aligned.m8n8.x2.shared.b16 {%0,%1}, [%2];"
                 : "=r"(r0), "=r"(r1) : "r"(addr));
}
__device__ __forceinline__ void mma16816(float* c, const u32* a, const u32* b) {
    asm volatile("mma.sync.aligned.m16n8k16.row.col.f32.f16.f16.f32 "
                 "{%0,%1,%2,%3}, {%4,%5,%6,%7}, {%8,%9}, {%0,%1,%2,%3};"
                 : "+f"(c[0]), "+f"(c[1]), "+f"(c[2]), "+f"(c[3])
                 : "r"(a[0]), "r"(a[1]), "r"(a[2]), "r"(a[3]), "r"(b[0]), "r"(b[1]));
}
// 2-way fp16 split: x = hi + lo exactly to ~2^-22
__device__ __forceinline__ void split2(float x, u16& h, u16& l) {
    __half hh = __float2half_rn(x);
    __half ll = __float2half_rn(x - __half2float(hh));
    h = __half_as_ushort(hh); l = __half_as_ushort(ll);
}
union H8 { u16 s[8]; uint4 v; };

// ---------------------------------------------------------------- zero scratch
__global__ void k_zero() {
    int i = blockIdx.x * blockDim.x + threadIdx.x;
    if (i < NLEV * KCODES * DIM) g_sums[i] = 0.f;
    if (i < NLEV * KCODES)       g_counts[i] = 0.f;
    if (i < NLEV)                g_loss_acc[i] = 0.0;
}

// ------------------------------------------------ codebook fp16 splits + ||C||^2
__global__ void k_cbsplit(const float* __restrict__ codebooks) {
    const int row = blockIdx.x;            // NLEV*KCODES
    const int e0  = threadIdx.x * 8;       // 128 threads
    const float* src = codebooks + (size_t)row * DIM + e0;
    float4 v0 = *(const float4*)src;
    float4 v1 = *(const float4*)(src + 4);
    float xs[8] = {v0.x, v0.y, v0.z, v0.w, v1.x, v1.y, v1.z, v1.w};
    H8 ph, pl;
    float s = 0.f;
#pragma unroll
    for (int i = 0; i < 8; i++) { s += xs[i] * xs[i]; split2(xs[i], ph.s[i], pl.s[i]); }
    size_t off = (size_t)row * DIM + e0;
    *(uint4*)(g_cbh + off) = ph.v;
    *(uint4*)(g_cbl + off) = pl.v;
#pragma unroll
    for (int o = 16; o; o >>= 1) s += __shfl_xor_sync(0xffffffffu, s, o);
    __shared__ float red[4];
    if ((threadIdx.x & 31) == 0) red[threadIdx.x >> 5] = s;
    __syncthreads();
    if (threadIdx.x == 0) g_c2[row] = red[0] + red[1] + red[2] + red[3];
}

// ------------------------------------------------ split z_e (level-0 A operand)
__global__ void k_split0(const float* __restrict__ z_e) {
    const int tok = blockIdx.x * 2 + (threadIdx.x >> 7);
    const size_t off = (size_t)tok * DIM + (threadIdx.x & 127) * 8;
    float4 v0 = *(const float4*)(z_e + off);
    float4 v1 = *(const float4*)(z_e + off + 4);
    float xs[8] = {v0.x, v0.y, v0.z, v0.w, v1.x, v1.y, v1.z, v1.w};
    H8 ph, pl;
#pragma unroll
    for (int i = 0; i < 8; i++) split2(xs[i], ph.s[i], pl.s[i]);
    *(uint4*)(g_ah + off) = ph.v;
    *(uint4*)(g_al + off) = pl.v;
}

// ---------------------------------------------------------------- assign (mma.sync fp16 2-split)
// Block: 64 tokens x 512 codes (ct loop: 4 tiles of 128). 256 threads = 8 warps:
// mw = warp&3 (16-token slice), nw = warp>>2 (64-code half).
// K-chunk 64 through smem (stride 72 halves, ldmatrix conflict-free).
// dot = hh + hl + lh + ll, fp32 accum -> fp32-equivalent accuracy.
#define ASTRIDE 72
#define SA_ELE (64 * ASTRIDE)
#define SB_ELE (128 * ASTRIDE)
#define SMEM_BYTES ((2 * SA_ELE + 2 * SB_ELE) * 2)   // 55296

__global__ void __launch_bounds__(256, 2) k_assign_mma(int level, float* __restrict__ out_idx) {
    extern __shared__ __align__(16) u16 dsm[];
    u16* sAh = dsm;
    u16* sAl = dsm + SA_ELE;
    u16* sBh = dsm + 2 * SA_ELE;
    u16* sBl = sBh + SB_ELE;

    const int tid = threadIdx.x, wid = tid >> 5, lane = tid & 31;
    const int mw = wid & 3, nw = wid >> 2;
    const int t0 = blockIdx.x * 64;
    const int tr = mw * 16;

    const u16* bh = g_cbh + (size_t)level * KCODES * DIM;
    const u16* bl = g_cbl + (size_t)level * KCODES * DIM;
    const float* c2p = g_c2 + level * KCODES;

    const int srow = tid >> 3, sg = tid & 7;     // staging: row, 8-half granule

    // ldmatrix base addresses (bytes, shared space)
    const u32 aAh = smem_u32(sAh), aAl = smem_u32(sAl);
    const u32 aBh = smem_u32(sBh), aBl = smem_u32(sBl);
    const int arow = tr + (lane & 15);
    const int acolx = (lane >> 4) * 8;
    const int brow0 = nw * 64 + (lane & 7);
    const int bcolx = ((lane >> 3) & 1) * 8;

    // running per-lane argmin: token A = tr + (lane>>2), token B = tr + 8 + (lane>>2)
    float mv0 = 3.4e38f, mv1 = 3.4e38f;
    int   mi0 = 0,       mi1 = 0;

    for (int ct = 0; ct < 4; ct++) {
        float c[8][4];
#pragma unroll
        for (int j = 0; j < 8; j++)
#pragma unroll
            for (int q = 0; q < 4; q++) c[j][q] = 0.f;

        for (int kc = 0; kc < 16; kc++) {
            const int d0 = kc * 64;
            __syncthreads();
            // stage A: rows srow, srow+32 for hi & lo
#pragma unroll
            for (int i = 0; i < 2; i++) {
                int r = srow + i * 32;
                size_t go = (size_t)(t0 + r) * DIM + d0 + sg * 8;
                *(uint4*)&sAh[r * ASTRIDE + sg * 8] = *(const uint4*)(g_ah + go);
                *(uint4*)&sAl[r * ASTRIDE + sg * 8] = *(const uint4*)(g_al + go);
            }
            // stage B: rows srow + {0,32,64,96} for hi & lo
#pragma unroll
            for (int i = 0; i < 4; i++) {
                int r = srow + i * 32;
                size_t go = (size_t)(ct * 128 + r) * DIM + d0 + sg * 8;
                *(uint4*)&sBh[r * ASTRIDE + sg * 8] = *(const uint4*)(bh + go);
                *(uint4*)&sBl[r * ASTRIDE + sg * 8] = *(const uint4*)(bl + go);
            }
            __syncthreads();

#pragma unroll
            for (int kk = 0; kk < 4; kk++) {
                const int k0 = kk * 16;
                u32 Ah[4], Al[4];
                const u32 aoff = (u32)((arow * ASTRIDE + acolx + k0) * 2);
                ldsm4(Ah[0], Ah[1], Ah[2], Ah[3], aAh + aoff);
                ldsm4(Al[0], Al[1], Al[2], Al[3], aAl + aoff);
#pragma unroll
                for (int j = 0; j < 8; j++) {
                    u32 Bh[2], Bl[2];
                    const u32 boff = (u32)(((brow0 + j * 8) * ASTRIDE + bcolx + k0) * 2);
                    ldsm2(Bh[0], Bh[1], aBh + boff);
                    ldsm2(Bl[0], Bl[1], aBl + boff);
                    mma16816(c[j], Ah, Bh);
                    mma16816(c[j], Ah, Bl);
                    mma16816(c[j], Al, Bh);
                    mma16816(c[j], Al, Bl);
                }
            }
        }

        // fold this ct's scores into running argmin (ascending code order)
#pragma unroll
        for (int j = 0; j < 8; j++) {
            const int id = ct * 128 + nw * 64 + j * 8 + 2 * (lane & 3);
            const float c2a = __ldg(c2p + id);
            const float c2b = __ldg(c2p + id + 1);
            float s0 = c2a - 2.f * c[j][0];          // token A, code id
            float s1 = c2b - 2.f * c[j][1];          // token A, code id+1
            float s2 = c2a - 2.f * c[j][2];          // token B, code id
            float s3 = c2b - 2.f * c[j][3];          // token B, code id+1
            if (s0 < mv0) { mv0 = s0; mi0 = id; }
            if (s1 < mv0) { mv0 = s1; mi0 = id + 1; }
            if (s2 < mv1) { mv1 = s2; mi1 = id; }
            if (s3 < mv1) { mv1 = s3; mi1 = id + 1; }
        }
    }

    // quad reduce (lanes sharing a row): codes differ across lanes -> tie-break lowest idx
#pragma unroll
    for (int off = 1; off <= 2; off <<= 1) {
        float ov0 = __shfl_xor_sync(0xffffffffu, mv0, off);
        int   oi0 = __shfl_xor_sync(0xffffffffu, mi0, off);
        float ov1 = __shfl_xor_sync(0xffffffffu, mv1, off);
        int   oi1 = __shfl_xor_sync(0xffffffffu, mi1, off);
        if (ov0 < mv0 || (ov0 == mv0 && oi0 < mi0)) { mv0 = ov0; mi0 = oi0; }
        if (ov1 < mv1 || (ov1 == mv1 && oi1 < mi1)) { mv1 = ov1; mi1 = oi1; }
    }

    __shared__ float smv[2][64];
    __shared__ int   smi[2][64];
    if ((lane & 3) == 0) {
        const int r = lane >> 2;
        smv[nw][tr + r] = mv0;     smi[nw][tr + r] = mi0;
        smv[nw][tr + 8 + r] = mv1; smi[nw][tr + 8 + r] = mi1;
    }
    __syncthreads();
    if (tid < 64) {
        float v0 = smv[0][tid]; int i0 = smi[0][tid];
        float v1 = smv[1][tid]; int i1 = smi[1][tid];
        int mi = (v1 < v0) ? i1 : i0;            // nw0 codes lower: tie keeps nw0
        g_idx[t0 + tid] = mi;
        out_idx[(size_t)level * NTOK + t0 + tid] = (float)mi;
    }
}

// ---------------------------------------------------------------- update
// 4 tokens/block; 64 threads/token, 16 floats/thread; red.v4 scatter;
// emits fp16 splits of the new residual for the next level's assign.
__global__ void __launch_bounds__(256) k_update(int level,
                                                const float* __restrict__ z_e,
                                                const float* __restrict__ codebooks,
                                                float* __restrict__ out_zq) {
    const int tid = threadIdx.x;
    const int tok = blockIdx.x * 4 + (tid >> 6);
    const int d   = (tid & 63) * 16;
    const float* rin = level ? g_residual : z_e;
    const int idx = g_idx[tok];
    const float* q = codebooks + ((size_t)level * KCODES + idx) * DIM + d;
    const float* r = rin + (size_t)tok * DIM + d;
    float* sums = g_sums + ((size_t)level * KCODES + idx) * DIM + d;
    float* rout = g_residual + (size_t)tok * DIM + d;
    float* zo   = out_zq + (size_t)tok * DIM + d;

    float ls = 0.f;
    H8 ph[2], pl[2];
#pragma unroll
    for (int v = 0; v < 4; v++) {
        float4 rv = *(const float4*)(r + v * 4);
        float4 qv = *(const float4*)(q + v * 4);
        float4 rq = make_float4(rv.x - qv.x, rv.y - qv.y, rv.z - qv.z, rv.w - qv.w);
        *(float4*)(rout + v * 4) = rq;
        if (level) {
            float4 z = *(const float4*)(zo + v * 4);
            z.x += qv.x; z.y += qv.y; z.z += qv.z; z.w += qv.w;
            *(float4*)(zo + v * 4) = z;
        } else {
            *(float4*)(zo + v * 4) = qv;
        }
        red4(sums + v * 4, rv);
        ls += rq.x * rq.x + rq.y * rq.y + rq.z * rq.z + rq.w * rq.w;
        if (level < 2) {
            const int g = v >> 1, e = (v & 1) * 4;
            split2(rq.x, ph[g].s[e + 0], pl[g].s[e + 0]);
            split2(rq.y, ph[g].s[e + 1], pl[g].s[e + 1]);
            split2(rq.z, ph[g].s[e + 2], pl[g].s[e + 2]);
            split2(rq.w, ph[g].s[e + 3], pl[g].s[e + 3]);
        }
    }
    if (level < 2) {
        const size_t off = (size_t)tok * DIM + d;
#pragma unroll
        for (int g = 0; g < 2; g++) {
            *(uint4*)(g_ah + off + g * 8) = ph[g].v;
            *(uint4*)(g_al + off + g * 8) = pl[g].v;
        }
    }
    if ((tid & 63) == 0) atomicAdd(g_counts + level * KCODES + idx, 1.0f);

#pragma unroll
    for (int o = 16; o; o >>= 1) ls += __shfl_xor_sync(0xffffffffu, ls, o);
    __shared__ float red[8];
    const int warp = tid >> 5, lane = tid & 31;
    if (lane == 0) red[warp] = ls;
    __syncthreads();
    if (tid < 8) {
        float v = red[tid];
#pragma unroll
        for (int o = 4; o; o >>= 1) v += __shfl_xor_sync(0xffu, v, o);
        if (tid == 0) atomicAdd(&g_loss_acc[level], (double)v);
    }
}

// ---------------------------------------------------------------- cs + n
__global__ void k_csn(const float* __restrict__ ema_cluster) {
    const int l = blockIdx.x;
    const int k = threadIdx.x;   // 512 threads
    float cs = DECAY * ema_cluster[l * KCODES + k] + OMD * g_counts[l * KCODES + k];
    g_cs[l * KCODES + k] = cs;
    float s = cs;
#pragma unroll
    for (int o = 16; o; o >>= 1) s += __shfl_xor_sync(0xffffffffu, s, o);
    __shared__ float red[16];
    const int warp = threadIdx.x >> 5, lane = threadIdx.x & 31;
    if (lane == 0) red[warp] = s;
    __syncthreads();
    if (threadIdx.x < 16) {
        float v = red[threadIdx.x];
#pragma unroll
        for (int o = 8; o; o >>= 1) v += __shfl_xor_sync(0xffffu, v, o);
        if (threadIdx.x == 0) g_n[l] = v;
    }
}

// ---------------------------------------------------------------- new codebooks + loss
__global__ void k_cb(const float* __restrict__ ema_w,
                     float* __restrict__ out_cb,
                     float* __restrict__ out_loss) {
    const int i = blockIdx.x * blockDim.x + threadIdx.x;
    if (i == 0) {
        double L = (0.25 * g_loss_acc[0] + 0.5 * g_loss_acc[1] + 1.0 * g_loss_acc[2])
                   * (1.0 / ((double)NTOK * (double)DIM));
        *out_loss = (float)L;
    }
    if (i >= NLEV * KCODES * DIM) return;
    const int row = i >> 10;
    const int l   = row >> 9;
    float w  = DECAY * ema_w[i] + OMD * g_sums[i];
    float cs = g_cs[row];
    float n  = g_n[l];
    float csn = (cs + EPSV) / (n + 0.00512f) * n;   // K*EPS = 512e-5
    out_cb[i] = w / csn;
}

// ---------------------------------------------------------------- launch
extern "C" void kernel_launch(void* const* d_in, const int* in_sizes, int n_in,
                              void* d_out, int out_size) {
    const float* z_e         = (const float*)d_in[0];
    const float* codebooks   = (const float*)d_in[1];
    const float* ema_cluster = (const float*)d_in[2];
    const float* ema_w       = (const float*)d_in[3];
    float* out = (float*)d_out;

    const size_t ZQ = (size_t)NTOK * DIM;
    float* out_zq   = out;
    float* out_loss = out + ZQ;
    float* out_idx  = out + ZQ + 1;
    float* out_cb   = out + ZQ + 1 + (size_t)NLEV * NTOK;

    cudaFuncSetAttribute(k_assign_mma, cudaFuncAttributeMaxDynamicSharedMemorySize, SMEM_BYTES);

    k_zero<<<(NLEV * KCODES * DIM + 255) / 256, 256>>>();
    k_cbsplit<<<NLEV * KCODES, 128>>>(codebooks);
    k_split0<<<NTOK / 2, 256>>>(z_e);
    for (int l = 0; l < NLEV; l++) {
        k_assign_mma<<<NTOK / 64, 256, SMEM_BYTES>>>(l, out_idx);
        k_update<<<NTOK / 4, 256>>>(l, z_e, codebooks, out_zq);
    }
    k_csn<<<NLEV, 512>>>(ema_cluster);
    k_cb<<<(NLEV * KCODES * DIM + 255) / 256, 256>>>(ema_w, out_cb, out_loss);
}

// round 9
// speedup vs baseline: 2.9803x; 1.2544x over previous
#include <cuda_runtime.h>
#include <cuda_fp16.h>
#include <cstdint>

#define NLEV   3
#define KCODES 512
#define DIM    1024
#define NTOK   65536           // 16 * 4096
#define DECAY  0.99f
#define OMD    0.01f
#define EPSV   1e-5f

typedef unsigned long long ull;
typedef unsigned int       u32;
typedef unsigned short     u16;

// ---- scratch (__device__ globals: the sanctioned no-alloc path) ----
static __device__ __align__(16) float g_residual[(size_t)NTOK * DIM];  // 268 MB
static __device__ __align__(16) u16   g_ah[(size_t)NTOK * DIM];        // 134 MB fp16 hi
static __device__ __align__(16) u16   g_al[(size_t)NTOK * DIM];        // 134 MB fp16 lo
static __device__ __align__(16) u16   g_cbh[NLEV * KCODES * DIM];
static __device__ __align__(16) u16   g_cbl[NLEV * KCODES * DIM];
static __device__ __align__(16) float g_sums[NLEV * KCODES * DIM];
static __device__ float  g_counts[NLEV * KCODES];
static __device__ float  g_c2[NLEV * KCODES];
static __device__ float  g_cs[NLEV * KCODES];
static __device__ float  g_n[NLEV];
static __device__ double g_loss_acc[NLEV];
static __device__ int    g_idx[NTOK];

__device__ __forceinline__ u32 smem_u32(const void* p) {
    u32 a;
    asm("{ .reg .u64 t; cvta.to.shared.u64 t, %1; cvt.u32.u64 %0, t; }" : "=r"(a) : "l"(p));
    return a;
}
__device__ __forceinline__ void red4(float* p, float4 v) {
    asm volatile("red.global.add.v4.f32 [%0], {%1,%2,%3,%4};"
                 :: "l"(p), "f"(v.x), "f"(v.y), "f"(v.z), "f"(v.w) : "memory");
}
__device__ __forceinline__ void ldsm4(u32& r0, u32& r1, u32& r2, u32& r3, u32 addr) {
    asm volatile("ldmatrix.sync.aligned.m8n8.x4.shared.b16 {%0,%1,%2,%3}, [%4];"
                 : "=r"(r0), "=r"(r1), "=r"(r2), "=r"(r3) : "r"(addr));
}
__device__ __forceinline__ void mma16816(float* c, const u32* a, const u32* b) {
    asm volatile("mma.sync.aligned.m16n8k16.row.col.f32.f16.f16.f32 "
                 "{%0,%1,%2,%3}, {%4,%5,%6,%7}, {%8,%9}, {%0,%1,%2,%3};"
                 : "+f"(c[0]), "+f"(c[1]), "+f"(c[2]), "+f"(c[3])
                 : "r"(a[0]), "r"(a[1]), "r"(a[2]), "r"(a[3]), "r"(b[0]), "r"(b[1]));
}
// 2-way fp16 split: x = hi + lo exactly to ~2^-22
__device__ __forceinline__ void split2(float x, u16& h, u16& l) {
    __half hh = __float2half_rn(x);
    __half ll = __float2half_rn(x - __half2float(hh));
    h = __half_as_ushort(hh); l = __half_as_ushort(ll);
}
union H8 { u16 s[8]; uint4 v; };

// ---------------------------------------------------------------- zero scratch
__global__ void k_zero() {
    int i = blockIdx.x * blockDim.x + threadIdx.x;
    if (i < NLEV * KCODES * DIM) g_sums[i] = 0.f;
    if (i < NLEV * KCODES)       g_counts[i] = 0.f;
    if (i < NLEV)                g_loss_acc[i] = 0.0;
}

// ------------------------------------------------ codebook fp16 splits + ||C||^2
__global__ void k_cbsplit(const float* __restrict__ codebooks) {
    const int row = blockIdx.x;            // NLEV*KCODES
    const int e0  = threadIdx.x * 8;       // 128 threads
    const float* src = codebooks + (size_t)row * DIM + e0;
    float4 v0 = *(const float4*)src;
    float4 v1 = *(const float4*)(src + 4);
    float xs[8] = {v0.x, v0.y, v0.z, v0.w, v1.x, v1.y, v1.z, v1.w};
    H8 ph, pl;
    float s = 0.f;
#pragma unroll
    for (int i = 0; i < 8; i++) { s += xs[i] * xs[i]; split2(xs[i], ph.s[i], pl.s[i]); }
    size_t off = (size_t)row * DIM + e0;
    *(uint4*)(g_cbh + off) = ph.v;
    *(uint4*)(g_cbl + off) = pl.v;
#pragma unroll
    for (int o = 16; o; o >>= 1) s += __shfl_xor_sync(0xffffffffu, s, o);
    __shared__ float red[4];
    if ((threadIdx.x & 31) == 0) red[threadIdx.x >> 5] = s;
    __syncthreads();
    if (threadIdx.x == 0) g_c2[row] = red[0] + red[1] + red[2] + red[3];
}

// ------------------------------------------------ split z_e (level-0 A operand)
__global__ void k_split0(const float* __restrict__ z_e) {
    const int tok = blockIdx.x * 2 + (threadIdx.x >> 7);
    const size_t off = (size_t)tok * DIM + (threadIdx.x & 127) * 8;
    float4 v0 = *(const float4*)(z_e + off);
    float4 v1 = *(const float4*)(z_e + off + 4);
    float xs[8] = {v0.x, v0.y, v0.z, v0.w, v1.x, v1.y, v1.z, v1.w};
    H8 ph, pl;
#pragma unroll
    for (int i = 0; i < 8; i++) split2(xs[i], ph.s[i], pl.s[i]);
    *(uint4*)(g_ah + off) = ph.v;
    *(uint4*)(g_al + off) = pl.v;
}

// ---------------------------------------------------------------- assign (mma.sync fp16 2-split)
// Block: 64 tokens x 512 codes (ct loop: 4 tiles of 128). 256 threads = 8 warps:
// mw = warp&3 (16-token slice), nw = warp>>2 (64-code half).
// K-chunk 64 through smem (stride 72 halves, ldmatrix conflict-free).
// dot = hh + hl + lh (ll term ~2^-22 rel, dropped), fp32 accum.
// B fragments loaded 2 code-groups at a time via ldmatrix.x4.
#define ASTRIDE 72
#define SA_ELE (64 * ASTRIDE)
#define SB_ELE (128 * ASTRIDE)
#define SMEM_BYTES ((2 * SA_ELE + 2 * SB_ELE) * 2)   // 55296

__global__ void __launch_bounds__(256, 2) k_assign_mma(int level, float* __restrict__ out_idx) {
    extern __shared__ __align__(16) u16 dsm[];
    u16* sAh = dsm;
    u16* sAl = dsm + SA_ELE;
    u16* sBh = dsm + 2 * SA_ELE;
    u16* sBl = sBh + SB_ELE;

    const int tid = threadIdx.x, wid = tid >> 5, lane = tid & 31;
    const int mw = wid & 3, nw = wid >> 2;
    const int t0 = blockIdx.x * 64;
    const int tr = mw * 16;

    const u16* bh = g_cbh + (size_t)level * KCODES * DIM;
    const u16* bl = g_cbl + (size_t)level * KCODES * DIM;
    const float* c2p = g_c2 + level * KCODES;

    const int srow = tid >> 3, sg = tid & 7;     // staging: row, 8-half granule

    // ldmatrix base addresses (bytes, shared space)
    const u32 aAh = smem_u32(sAh), aAl = smem_u32(sAl);
    const u32 aBh = smem_u32(sBh), aBl = smem_u32(sBl);
    const int arow = tr + (lane & 15);
    const int acolx = (lane >> 4) * 8;
    // B x4 addressing: matid 0..3 -> (selj, selk); covers 2 code groups per ldsm4
    const int matid = lane >> 3;
    const int selj = matid >> 1, selk = matid & 1;
    const int brow_b = nw * 64 + selj * 8 + (lane & 7);   // + jp*16
    const int bcol_b = selk * 8;                          // + k0

    // running per-lane argmin: token A = tr + (lane>>2), token B = tr + 8 + (lane>>2)
    float mv0 = 3.4e38f, mv1 = 3.4e38f;
    int   mi0 = 0,       mi1 = 0;

    for (int ct = 0; ct < 4; ct++) {
        float c[8][4];
#pragma unroll
        for (int j = 0; j < 8; j++)
#pragma unroll
            for (int q = 0; q < 4; q++) c[j][q] = 0.f;

        for (int kc = 0; kc < 16; kc++) {
            const int d0 = kc * 64;
            __syncthreads();
            // stage A: rows srow, srow+32 for hi & lo
#pragma unroll
            for (int i = 0; i < 2; i++) {
                int r = srow + i * 32;
                size_t go = (size_t)(t0 + r) * DIM + d0 + sg * 8;
                *(uint4*)&sAh[r * ASTRIDE + sg * 8] = *(const uint4*)(g_ah + go);
                *(uint4*)&sAl[r * ASTRIDE + sg * 8] = *(const uint4*)(g_al + go);
            }
            // stage B: rows srow + {0,32,64,96} for hi & lo
#pragma unroll
            for (int i = 0; i < 4; i++) {
                int r = srow + i * 32;
                size_t go = (size_t)(ct * 128 + r) * DIM + d0 + sg * 8;
                *(uint4*)&sBh[r * ASTRIDE + sg * 8] = *(const uint4*)(bh + go);
                *(uint4*)&sBl[r * ASTRIDE + sg * 8] = *(const uint4*)(bl + go);
            }
            __syncthreads();

#pragma unroll
            for (int kk = 0; kk < 4; kk++) {
                const int k0 = kk * 16;
                u32 Ah[4], Al[4];
                const u32 aoff = (u32)((arow * ASTRIDE + acolx + k0) * 2);
                ldsm4(Ah[0], Ah[1], Ah[2], Ah[3], aAh + aoff);
                ldsm4(Al[0], Al[1], Al[2], Al[3], aAl + aoff);
#pragma unroll
                for (int jp = 0; jp < 4; jp++) {
                    u32 Bh[4], Bl[4];
                    const u32 boff = (u32)(((brow_b + jp * 16) * ASTRIDE + bcol_b + k0) * 2);
                    ldsm4(Bh[0], Bh[1], Bh[2], Bh[3], aBh + boff);
                    ldsm4(Bl[0], Bl[1], Bl[2], Bl[3], aBl + boff);
                    mma16816(c[2 * jp],     Ah, &Bh[0]);
                    mma16816(c[2 * jp],     Ah, &Bl[0]);
                    mma16816(c[2 * jp],     Al, &Bh[0]);
                    mma16816(c[2 * jp + 1], Ah, &Bh[2]);
                    mma16816(c[2 * jp + 1], Ah, &Bl[2]);
                    mma16816(c[2 * jp + 1], Al, &Bh[2]);
                }
            }
        }

        // fold this ct's scores into running argmin (ascending code order)
#pragma unroll
        for (int j = 0; j < 8; j++) {
            const int id = ct * 128 + nw * 64 + j * 8 + 2 * (lane & 3);
            const float c2a = __ldg(c2p + id);
            const float c2b = __ldg(c2p + id + 1);
            float s0 = c2a - 2.f * c[j][0];          // token A, code id
            float s1 = c2b - 2.f * c[j][1];          // token A, code id+1
            float s2 = c2a - 2.f * c[j][2];          // token B, code id
            float s3 = c2b - 2.f * c[j][3];          // token B, code id+1
            if (s0 < mv0) { mv0 = s0; mi0 = id; }
            if (s1 < mv0) { mv0 = s1; mi0 = id + 1; }
            if (s2 < mv1) { mv1 = s2; mi1 = id; }
            if (s3 < mv1) { mv1 = s3; mi1 = id + 1; }
        }
    }

    // quad reduce (lanes sharing a row): tie-break lowest idx
#pragma unroll
    for (int off = 1; off <= 2; off <<= 1) {
        float ov0 = __shfl_xor_sync(0xffffffffu, mv0, off);
        int   oi0 = __shfl_xor_sync(0xffffffffu, mi0, off);
        float ov1 = __shfl_xor_sync(0xffffffffu, mv1, off);
        int   oi1 = __shfl_xor_sync(0xffffffffu, mi1, off);
        if (ov0 < mv0 || (ov0 == mv0 && oi0 < mi0)) { mv0 = ov0; mi0 = oi0; }
        if (ov1 < mv1 || (ov1 == mv1 && oi1 < mi1)) { mv1 = ov1; mi1 = oi1; }
    }

    __shared__ float smv[2][64];
    __shared__ int   smi[2][64];
    if ((lane & 3) == 0) {
        const int r = lane >> 2;
        smv[nw][tr + r] = mv0;     smi[nw][tr + r] = mi0;
        smv[nw][tr + 8 + r] = mv1; smi[nw][tr + 8 + r] = mi1;
    }
    __syncthreads();
    if (tid < 64) {
        float v0 = smv[0][tid]; int i0 = smi[0][tid];
        float v1 = smv[1][tid]; int i1 = smi[1][tid];
        int mi = (v1 < v0) ? i1 : i0;            // nw0 codes lower: tie keeps nw0
        g_idx[t0 + tid] = mi;
        out_idx[(size_t)level * NTOK + t0 + tid] = (float)mi;
    }
}

// ---------------------------------------------------------------- update
// 4 tokens/block; 64 threads/token, 16 floats/thread; red.v4 scatter;
// emits fp16 splits of the new residual for the next level's assign.
__global__ void __launch_bounds__(256) k_update(int level,
                                                const float* __restrict__ z_e,
                                                const float* __restrict__ codebooks,
                                                float* __restrict__ out_zq) {
    const int tid = threadIdx.x;
    const int tok = blockIdx.x * 4 + (tid >> 6);
    const int d   = (tid & 63) * 16;
    const float* rin = level ? g_residual : z_e;
    const int idx = g_idx[tok];
    const float* q = codebooks + ((size_t)level * KCODES + idx) * DIM + d;
    const float* r = rin + (size_t)tok * DIM + d;
    float* sums = g_sums + ((size_t)level * KCODES + idx) * DIM + d;
    float* rout = g_residual + (size_t)tok * DIM + d;
    float* zo   = out_zq + (size_t)tok * DIM + d;

    float ls = 0.f;
    H8 ph[2], pl[2];
#pragma unroll
    for (int v = 0; v < 4; v++) {
        float4 rv = *(const float4*)(r + v * 4);
        float4 qv = *(const float4*)(q + v * 4);
        float4 rq = make_float4(rv.x - qv.x, rv.y - qv.y, rv.z - qv.z, rv.w - qv.w);
        *(float4*)(rout + v * 4) = rq;
        if (level) {
            float4 z = *(const float4*)(zo + v * 4);
            z.x += qv.x; z.y += qv.y; z.z += qv.z; z.w += qv.w;
            *(float4*)(zo + v * 4) = z;
        } else {
            *(float4*)(zo + v * 4) = qv;
        }
        red4(sums + v * 4, rv);
        ls += rq.x * rq.x + rq.y * rq.y + rq.z * rq.z + rq.w * rq.w;
        if (level < 2) {
            const int g = v >> 1, e = (v & 1) * 4;
            split2(rq.x, ph[g].s[e + 0], pl[g].s[e + 0]);
            split2(rq.y, ph[g].s[e + 1], pl[g].s[e + 1]);
            split2(rq.z, ph[g].s[e + 2], pl[g].s[e + 2]);
            split2(rq.w, ph[g].s[e + 3], pl[g].s[e + 3]);
        }
    }
    if (level < 2) {
        const size_t off = (size_t)tok * DIM + d;
#pragma unroll
        for (int g = 0; g < 2; g++) {
            *(uint4*)(g_ah + off + g * 8) = ph[g].v;
            *(uint4*)(g_al + off + g * 8) = pl[g].v;
        }
    }
    if ((tid & 63) == 0) atomicAdd(g_counts + level * KCODES + idx, 1.0f);

#pragma unroll
    for (int o = 16; o; o >>= 1) ls += __shfl_xor_sync(0xffffffffu, ls, o);
    __shared__ float red[8];
    const int warp = tid >> 5, lane = tid & 31;
    if (lane == 0) red[warp] = ls;
    __syncthreads();
    if (tid < 8) {
        float v = red[tid];
#pragma unroll
        for (int o = 4; o; o >>= 1) v += __shfl_xor_sync(0xffu, v, o);
        if (tid == 0) atomicAdd(&g_loss_acc[level], (double)v);
    }
}

// ---------------------------------------------------------------- cs + n
__global__ void k_csn(const float* __restrict__ ema_cluster) {
    const int l = blockIdx.x;
    const int k = threadIdx.x;   // 512 threads
    float cs = DECAY * ema_cluster[l * KCODES + k] + OMD * g_counts[l * KCODES + k];
    g_cs[l * KCODES + k] = cs;
    float s = cs;
#pragma unroll
    for (int o = 16; o; o >>= 1) s += __shfl_xor_sync(0xffffffffu, s, o);
    __shared__ float red[16];
    const int warp = threadIdx.x >> 5, lane = threadIdx.x & 31;
    if (lane == 0) red[warp] = s;
    __syncthreads();
    if (threadIdx.x < 16) {
        float v = red[threadIdx.x];
#pragma unroll
        for (int o = 8; o; o >>= 1) v += __shfl_xor_sync(0xffffu, v, o);
        if (threadIdx.x == 0) g_n[l] = v;
    }
}

// ---------------------------------------------------------------- new codebooks + loss
__global__ void k_cb(const float* __restrict__ ema_w,
                     float* __restrict__ out_cb,
                     float* __restrict__ out_loss) {
    const int i = blockIdx.x * blockDim.x + threadIdx.x;
    if (i == 0) {
        double L = (0.25 * g_loss_acc[0] + 0.5 * g_loss_acc[1] + 1.0 * g_loss_acc[2])
                   * (1.0 / ((double)NTOK * (double)DIM));
        *out_loss = (float)L;
    }
    if (i >= NLEV * KCODES * DIM) return;
    const int row = i >> 10;
    const int l   = row >> 9;
    float w  = DECAY * ema_w[i] + OMD * g_sums[i];
    float cs = g_cs[row];
    float n  = g_n[l];
    float csn = (cs + EPSV) / (n + 0.00512f) * n;   // K*EPS = 512e-5
    out_cb[i] = w / csn;
}

// ---------------------------------------------------------------- launch
extern "C" void kernel_launch(void* const* d_in, const int* in_sizes, int n_in,
                              void* d_out, int out_size) {
    const float* z_e         = (const float*)d_in[0];
    const float* codebooks   = (const float*)d_in[1];
    const float* ema_cluster = (const float*)d_in[2];
    const float* ema_w       = (const float*)d_in[3];
    float* out = (float*)d_out;

    const size_t ZQ = (size_t)NTOK * DIM;
    float* out_zq   = out;
    float* out_loss = out + ZQ;
    float* out_idx  = out + ZQ + 1;
    float* out_cb   = out + ZQ + 1 + (size_t)NLEV * NTOK;

    cudaFuncSetAttribute(k_assign_mma, cudaFuncAttributeMaxDynamicSharedMemorySize, SMEM_BYTES);

    k_zero<<<(NLEV * KCODES * DIM + 255) / 256, 256>>>();
    k_cbsplit<<<NLEV * KCODES, 128>>>(codebooks);
    k_split0<<<NTOK / 2, 256>>>(z_e);
    for (int l = 0; l < NLEV; l++) {
        k_assign_mma<<<NTOK / 64, 256, SMEM_BYTES>>>(l, out_idx);
        k_update<<<NTOK / 4, 256>>>(l, z_e, codebooks, out_zq);
    }
    k_csn<<<NLEV, 512>>>(ema_cluster);
    k_cb<<<(NLEV * KCODES * DIM + 255) / 256, 256>>>(ema_w, out_cb, out_loss);
}

// round 11
// speedup vs baseline: 3.5742x; 1.1993x over previous
#include <cuda_runtime.h>
#include <cuda_fp16.h>
#include <cstdint>

#define NLEV   3
#define KCODES 512
#define DIM    1024
#define NTOK   65536           // 16 * 4096
#define DECAY  0.99f
#define OMD    0.01f
#define EPSV   1e-5f

typedef unsigned long long ull;
typedef unsigned int       u32;
typedef unsigned short     u16;

// ---- scratch (__device__ globals: the sanctioned no-alloc path) ----
static __device__ __align__(16) float g_residual[(size_t)NTOK * DIM];   // 268 MB
static __device__ __align__(16) u16   g_ah[(size_t)NTOK * DIM];         // 134 MB fp16 hi
static __device__ __align__(16) u16   g_cbh[NLEV * KCODES * DIM];       // 3 MB fp16 hi
static __device__ __align__(16) float g_score[(size_t)NTOK * KCODES];   // 134 MB
static __device__ __align__(16) float g_sums[NLEV * KCODES * DIM];      // 6 MB
static __device__ float  g_counts[NLEV * KCODES];
static __device__ float  g_c2[NLEV * KCODES];
static __device__ u32    g_c2max[NLEV];
static __device__ float  g_cs[NLEV * KCODES];
static __device__ float  g_n[NLEV];
static __device__ double g_loss_acc[NLEV];

__device__ __forceinline__ u32 smem_u32(const void* p) {
    u32 a;
    asm("{ .reg .u64 t; cvta.to.shared.u64 t, %1; cvt.u32.u64 %0, t; }" : "=r"(a) : "l"(p));
    return a;
}
__device__ __forceinline__ void red4(float* p, float4 v) {
    asm volatile("red.global.add.v4.f32 [%0], {%1,%2,%3,%4};"
                 :: "l"(p), "f"(v.x), "f"(v.y), "f"(v.z), "f"(v.w) : "memory");
}
__device__ __forceinline__ void ldsm4(u32& r0, u32& r1, u32& r2, u32& r3, u32 addr) {
    asm volatile("ldmatrix.sync.aligned.m8n8.x4.shared.b16 {%0,%1,%2,%3}, [%4];"
                 : "=r"(r0), "=r"(r1), "=r"(r2), "=r"(r3) : "r"(addr));
}
__device__ __forceinline__ void mma16816(float* c, const u32* a, const u32* b) {
    asm volatile("mma.sync.aligned.m16n8k16.row.col.f32.f16.f16.f32 "
                 "{%0,%1,%2,%3}, {%4,%5,%6,%7}, {%8,%9}, {%0,%1,%2,%3};"
                 : "+f"(c[0]), "+f"(c[1]), "+f"(c[2]), "+f"(c[3])
                 : "r"(a[0]), "r"(a[1]), "r"(a[2]), "r"(a[3]), "r"(b[0]), "r"(b[1]));
}
union H8 { u16 s[8]; uint4 v; };

// ---------------------------------------------------------------- zero scratch
__global__ void k_zero() {
    int i = blockIdx.x * blockDim.x + threadIdx.x;
    if (i < NLEV * KCODES * DIM) g_sums[i] = 0.f;
    if (i < NLEV * KCODES)       g_counts[i] = 0.f;
    if (i < NLEV)                { g_loss_acc[i] = 0.0; g_c2max[i] = 0u; }
}

// ------------------------------------------------ codebook fp16-hi + ||C||^2 + max
__global__ void k_cbsplit(const float* __restrict__ codebooks) {
    const int row = blockIdx.x;            // NLEV*KCODES
    const int e0  = threadIdx.x * 8;       // 128 threads
    const float* src = codebooks + (size_t)row * DIM + e0;
    float4 v0 = *(const float4*)src;
    float4 v1 = *(const float4*)(src + 4);
    float xs[8] = {v0.x, v0.y, v0.z, v0.w, v1.x, v1.y, v1.z, v1.w};
    H8 ph;
    float s = 0.f;
#pragma unroll
    for (int i = 0; i < 8; i++) {
        s += xs[i] * xs[i];
        ph.s[i] = __half_as_ushort(__float2half_rn(xs[i]));
    }
    *(uint4*)(g_cbh + (size_t)row * DIM + e0) = ph.v;
#pragma unroll
    for (int o = 16; o; o >>= 1) s += __shfl_xor_sync(0xffffffffu, s, o);
    __shared__ float red[4];
    if ((threadIdx.x & 31) == 0) red[threadIdx.x >> 5] = s;
    __syncthreads();
    if (threadIdx.x == 0) {
        float c2 = red[0] + red[1] + red[2] + red[3];
        g_c2[row] = c2;
        atomicMax(&g_c2max[row >> 9], __float_as_uint(c2));   // c2 >= 0
    }
}

// ------------------------------------------------ fp16-hi of z_e (level-0 A operand)
__global__ void k_split0(const float* __restrict__ z_e) {
    const int tok = blockIdx.x * 2 + (threadIdx.x >> 7);
    const size_t off = (size_t)tok * DIM + (threadIdx.x & 127) * 8;
    float4 v0 = *(const float4*)(z_e + off);
    float4 v1 = *(const float4*)(z_e + off + 4);
    float xs[8] = {v0.x, v0.y, v0.z, v0.w, v1.x, v1.y, v1.z, v1.w};
    H8 ph;
#pragma unroll
    for (int i = 0; i < 8; i++) ph.s[i] = __half_as_ushort(__float2half_rn(xs[i]));
    *(uint4*)(g_ah + off) = ph.v;
}

// ---------------------------------------------------------------- phase 1: hh scores
// Block: 64 tokens x 512 codes (ct loop: 4x128). 8 warps: mw=warp&3, nw=warp>>2.
// score[t][c] = ||C_c||^2 - 2 * dot(hi(r_t), hi(C_c)), written to g_score.
#define ASTRIDE 72
#define SA_ELE (64 * ASTRIDE)
#define SB_ELE (128 * ASTRIDE)
#define SMEM_SCORE ((SA_ELE + SB_ELE) * 2)   // 27648 bytes

__global__ void __launch_bounds__(256, 2) k_score(int level) {
    extern __shared__ __align__(16) u16 dsm[];
    u16* sA = dsm;
    u16* sB = dsm + SA_ELE;

    const int tid = threadIdx.x, wid = tid >> 5, lane = tid & 31;
    const int mw = wid & 3, nw = wid >> 2;
    const int t0 = blockIdx.x * 64;
    const int tr = mw * 16;

    const u16* bh = g_cbh + (size_t)level * KCODES * DIM;
    const float* c2p = g_c2 + level * KCODES;

    const int srow = tid >> 3, sg = tid & 7;

    const u32 aA = smem_u32(sA), aB = smem_u32(sB);
    const int arow = tr + (lane & 15);
    const int acolx = (lane >> 4) * 8;
    const int matid = lane >> 3;
    const int selj = matid >> 1, selk = matid & 1;
    const int brow_b = nw * 64 + selj * 8 + (lane & 7);
    const int bcol_b = selk * 8;

    for (int ct = 0; ct < 4; ct++) {
        float c[8][4];
#pragma unroll
        for (int j = 0; j < 8; j++)
#pragma unroll
            for (int q = 0; q < 4; q++) c[j][q] = 0.f;

        for (int kc = 0; kc < 16; kc++) {
            const int d0 = kc * 64;
            __syncthreads();
#pragma unroll
            for (int i = 0; i < 2; i++) {
                int r = srow + i * 32;
                *(uint4*)&sA[r * ASTRIDE + sg * 8] =
                    *(const uint4*)(g_ah + (size_t)(t0 + r) * DIM + d0 + sg * 8);
            }
#pragma unroll
            for (int i = 0; i < 4; i++) {
                int r = srow + i * 32;
                *(uint4*)&sB[r * ASTRIDE + sg * 8] =
                    *(const uint4*)(bh + (size_t)(ct * 128 + r) * DIM + d0 + sg * 8);
            }
            __syncthreads();

#pragma unroll
            for (int kk = 0; kk < 4; kk++) {
                const int k0 = kk * 16;
                u32 Ah[4];
                ldsm4(Ah[0], Ah[1], Ah[2], Ah[3], aA + (u32)((arow * ASTRIDE + acolx + k0) * 2));
#pragma unroll
                for (int jp = 0; jp < 4; jp++) {
                    u32 Bh[4];
                    ldsm4(Bh[0], Bh[1], Bh[2], Bh[3],
                          aB + (u32)(((brow_b + jp * 16) * ASTRIDE + bcol_b + k0) * 2));
                    mma16816(c[2 * jp],     Ah, &Bh[0]);
                    mma16816(c[2 * jp + 1], Ah, &Bh[2]);
                }
            }
        }

        // write scores for this 128-code tile
        const int rowA = t0 + tr + (lane >> 2);
#pragma unroll
        for (int j = 0; j < 8; j++) {
            const int id = ct * 128 + nw * 64 + j * 8 + 2 * (lane & 3);
            const float c2a = __ldg(c2p + id);
            const float c2b = __ldg(c2p + id + 1);
            float2 pa = make_float2(c2a - 2.f * c[j][0], c2b - 2.f * c[j][1]);
            float2 pb = make_float2(c2a - 2.f * c[j][2], c2b - 2.f * c[j][3]);
            *(float2*)(g_score + (size_t)rowA * KCODES + id) = pa;
            *(float2*)(g_score + (size_t)(rowA + 8) * KCODES + id) = pb;
        }
    }
}

// ---------------------------------------------------------------- phase 2: pick + update (fused)
// One warp per token. Finds hh-min, rescores candidates within a rigorous
// margin using exact fp32 dots, then performs the full EMA/residual update.
__global__ void __launch_bounds__(256) k_pick(int level,
                                              const float* __restrict__ z_e,
                                              const float* __restrict__ codebooks,
                                              float* __restrict__ out_zq,
                                              float* __restrict__ out_idx) {
    const int wid = threadIdx.x >> 5, lane = threadIdx.x & 31;
    const int tok = blockIdx.x * 8 + wid;
    const float* c2p = g_c2 + level * KCODES;
    const float* cbl = codebooks + (size_t)level * KCODES * DIM;
    const float* srow = g_score + (size_t)tok * KCODES;

    // hh scores: lane covers codes {lane*4 + i*128 + (0..3)}
    float s[16];
    float mv = 3.4e38f; int mi = 0;
#pragma unroll
    for (int i = 0; i < 4; i++) {
        float4 v = *(const float4*)(srow + lane * 4 + i * 128);
        const int c0 = lane * 4 + i * 128;
        s[i * 4 + 0] = v.x; s[i * 4 + 1] = v.y; s[i * 4 + 2] = v.z; s[i * 4 + 3] = v.w;
        if (v.x < mv || (v.x == mv && c0     < mi)) { mv = v.x; mi = c0; }
        if (v.y < mv || (v.y == mv && c0 + 1 < mi)) { mv = v.y; mi = c0 + 1; }
        if (v.z < mv || (v.z == mv && c0 + 2 < mi)) { mv = v.z; mi = c0 + 2; }
        if (v.w < mv || (v.w == mv && c0 + 3 < mi)) { mv = v.w; mi = c0 + 3; }
    }
#pragma unroll
    for (int o = 16; o; o >>= 1) {
        float ov = __shfl_xor_sync(0xffffffffu, mv, o);
        int   oi = __shfl_xor_sync(0xffffffffu, mi, o);
        if (ov < mv || (ov == mv && oi < mi)) { mv = ov; mi = oi; }
    }

    // residual: lane holds dims [lane*32, lane*32+32)
    const float* rin = (level ? g_residual : z_e) + (size_t)tok * DIM + lane * 32;
    float4 r4[8];
    float r2 = 0.f;
#pragma unroll
    for (int v = 0; v < 8; v++) {
        r4[v] = *(const float4*)(rin + v * 4);
        r2 += r4[v].x * r4[v].x + r4[v].y * r4[v].y + r4[v].z * r4[v].z + r4[v].w * r4[v].w;
    }
#pragma unroll
    for (int o = 16; o; o >>= 1) r2 += __shfl_xor_sync(0xffffffffu, r2, o);

    const float cmax = sqrtf(__uint_as_float(g_c2max[level]));
    const float thr = mv + 0.00390625f * sqrtf(r2) * cmax + 0.5f;   // min + 2B

    // exact rescore of candidates
    float bestv = 3.4e38f; int besti = 0;
#pragma unroll
    for (int i = 0; i < 16; i++) {
        const int cid_l = lane * 4 + (i >> 2) * 128 + (i & 3);
        u32 m = __ballot_sync(0xffffffffu, s[i] <= thr);
        while (m) {
            const int src = __ffs(m) - 1; m &= m - 1;
            const int cid = __shfl_sync(0xffffffffu, cid_l, src);
            const float* crow = cbl + (size_t)cid * DIM + lane * 32;
            float dot = 0.f;
#pragma unroll
            for (int v = 0; v < 8; v++) {
                float4 q = __ldg((const float4*)(crow + v * 4));
                dot += r4[v].x * q.x + r4[v].y * q.y + r4[v].z * q.z + r4[v].w * q.w;
            }
#pragma unroll
            for (int o = 16; o; o >>= 1) dot += __shfl_xor_sync(0xffffffffu, dot, o);
            const float sc = __ldg(c2p + cid) - 2.f * dot;
            if (sc < bestv || (sc == bestv && cid < besti)) { bestv = sc; besti = cid; }
        }
    }

    // ---- fused update ----
    const float* qrow = cbl + (size_t)besti * DIM + lane * 32;
    float* sums = g_sums + ((size_t)(level * KCODES + besti)) * DIM + lane * 32;
    float* rout = g_residual + (size_t)tok * DIM + lane * 32;
    float* zo   = out_zq + (size_t)tok * DIM + lane * 32;

    float ls = 0.f;
    H8 ph[4];
#pragma unroll
    for (int v = 0; v < 8; v++) {
        float4 q = __ldg((const float4*)(qrow + v * 4));
        float4 rq = make_float4(r4[v].x - q.x, r4[v].y - q.y, r4[v].z - q.z, r4[v].w - q.w);
        ls += rq.x * rq.x + rq.y * rq.y + rq.z * rq.z + rq.w * rq.w;
        if (level < 2) {
            *(float4*)(rout + v * 4) = rq;
            const int g = v >> 1, e = (v & 1) * 4;
            ph[g].s[e + 0] = __half_as_ushort(__float2half_rn(rq.x));
            ph[g].s[e + 1] = __half_as_ushort(__float2half_rn(rq.y));
            ph[g].s[e + 2] = __half_as_ushort(__float2half_rn(rq.z));
            ph[g].s[e + 3] = __half_as_ushort(__float2half_rn(rq.w));
        }
        red4(sums + v * 4, r4[v]);
        float4 z;
        if (level) {
            z = *(const float4*)(zo + v * 4);
            z.x += q.x; z.y += q.y; z.z += q.z; z.w += q.w;
        } else {
            z = q;
        }
        *(float4*)(zo + v * 4) = z;
    }
    if (level < 2) {
        u16* ao = g_ah + (size_t)tok * DIM + lane * 32;
#pragma unroll
        for (int g = 0; g < 4; g++) *(uint4*)(ao + g * 8) = ph[g].v;
    }
    if (lane == 0) {
        atomicAdd(g_counts + level * KCODES + besti, 1.0f);
        out_idx[(size_t)level * NTOK + tok] = (float)besti;
    }

    // block loss reduction -> one double atomic
#pragma unroll
    for (int o = 16; o; o >>= 1) ls += __shfl_xor_sync(0xffffffffu, ls, o);
    __shared__ float red[8];
    if (lane == 0) red[wid] = ls;
    __syncthreads();
    if (threadIdx.x < 8) {
        float v = red[threadIdx.x];
#pragma unroll
        for (int o = 4; o; o >>= 1) v += __shfl_xor_sync(0xffu, v, o);
        if (threadIdx.x == 0) atomicAdd(&g_loss_acc[level], (double)v);
    }
}

// ---------------------------------------------------------------- cs + n
__global__ void k_csn(const float* __restrict__ ema_cluster) {
    const int l = blockIdx.x;
    const int k = threadIdx.x;   // 512 threads
    float cs = DECAY * ema_cluster[l * KCODES + k] + OMD * g_counts[l * KCODES + k];
    g_cs[l * KCODES + k] = cs;
    float s = cs;
#pragma unroll
    for (int o = 16; o; o >>= 1) s += __shfl_xor_sync(0xffffffffu, s, o);
    __shared__ float red[16];
    const int warp = threadIdx.x >> 5, lane = threadIdx.x & 31;
    if (lane == 0) red[warp] = s;
    __syncthreads();
    if (threadIdx.x < 16) {
        float v = red[threadIdx.x];
#pragma unroll
        for (int o = 8; o; o >>= 1) v += __shfl_xor_sync(0xffffu, v, o);
        if (threadIdx.x == 0) g_n[l] = v;
    }
}

// ---------------------------------------------------------------- new codebooks + loss
__global__ void k_cb(const float* __restrict__ ema_w,
                     float* __restrict__ out_cb,
                     float* __restrict__ out_loss) {
    const int i = blockIdx.x * blockDim.x + threadIdx.x;
    if (i == 0) {
        double L = (0.25 * g_loss_acc[0] + 0.5 * g_loss_acc[1] + 1.0 * g_loss_acc[2])
                   * (1.0 / ((double)NTOK * (double)DIM));
        *out_loss = (float)L;
    }
    if (i >= NLEV * KCODES * DIM) return;
    const int row = i >> 10;
    const int l   = row >> 9;
    float w  = DECAY * ema_w[i] + OMD * g_sums[i];
    float cs = g_cs[row];
    float n  = g_n[l];
    float csn = (cs + EPSV) / (n + 0.00512f) * n;   // K*EPS = 512e-5
    out_cb[i] = w / csn;
}

// ---------------------------------------------------------------- launch
extern "C" void kernel_launch(void* const* d_in, const int* in_sizes, int n_in,
                              void* d_out, int out_size) {
    const float* z_e         = (const float*)d_in[0];
    const float* codebooks   = (const float*)d_in[1];
    const float* ema_cluster = (const float*)d_in[2];
    const float* ema_w       = (const float*)d_in[3];
    float* out = (float*)d_out;

    const size_t ZQ = (size_t)NTOK * DIM;
    float* out_zq   = out;
    float* out_loss = out + ZQ;
    float* out_idx  = out + ZQ + 1;
    float* out_cb   = out + ZQ + 1 + (size_t)NLEV * NTOK;

    cudaFuncSetAttribute(k_score, cudaFuncAttributeMaxDynamicSharedMemorySize, SMEM_SCORE);

    k_zero<<<(NLEV * KCODES * DIM + 255) / 256, 256>>>();
    k_cbsplit<<<NLEV * KCODES, 128>>>(codebooks);
    k_split0<<<NTOK / 2, 256>>>(z_e);
    for (int l = 0; l < NLEV; l++) {
        k_score<<<NTOK / 64, 256, SMEM_SCORE>>>(l);
        k_pick<<<NTOK / 8, 256>>>(l, z_e, codebooks, out_zq, out_idx);
    }
    k_csn<<<NLEV, 512>>>(ema_cluster);
    k_cb<<<(NLEV * KCODES * DIM + 255) / 256, 256>>>(ema_w, out_cb, out_loss);
}

// round 12
// speedup vs baseline: 4.4056x; 1.2326x over previous
#include <cuda_runtime.h>
#include <cuda_fp16.h>
#include <cstdint>

#define NLEV   3
#define KCODES 512
#define DIM    1024
#define NTOK   65536           // 16 * 4096
#define DECAY  0.99f
#define OMD    0.01f
#define EPSV   1e-5f

typedef unsigned long long ull;
typedef unsigned int       u32;
typedef unsigned short     u16;

// ---- scratch (__device__ globals: the sanctioned no-alloc path) ----
static __device__ __align__(16) float g_residual[(size_t)NTOK * DIM];   // 268 MB
static __device__ __align__(16) u16   g_ah[(size_t)NTOK * DIM];         // 134 MB fp16 hi
static __device__ __align__(16) u16   g_cbh[NLEV * KCODES * DIM];       // 3 MB fp16 hi
static __device__ __align__(16) u16   g_scoreh[(size_t)NTOK * KCODES];  // 67 MB fp16 scores
static __device__ __align__(16) float g_sums[NLEV * KCODES * DIM];      // 6 MB
static __device__ float  g_counts[NLEV * KCODES];
static __device__ float  g_c2[NLEV * KCODES];
static __device__ u32    g_c2max[NLEV];
static __device__ float  g_cs[NLEV * KCODES];
static __device__ float  g_n[NLEV];
static __device__ double g_loss_acc[NLEV];

__device__ __forceinline__ u32 smem_u32(const void* p) {
    u32 a;
    asm("{ .reg .u64 t; cvta.to.shared.u64 t, %1; cvt.u32.u64 %0, t; }" : "=r"(a) : "l"(p));
    return a;
}
__device__ __forceinline__ void red4(float* p, float4 v) {
    asm volatile("red.global.add.v4.f32 [%0], {%1,%2,%3,%4};"
                 :: "l"(p), "f"(v.x), "f"(v.y), "f"(v.z), "f"(v.w) : "memory");
}
__device__ __forceinline__ void ldsm4(u32& r0, u32& r1, u32& r2, u32& r3, u32 addr) {
    asm volatile("ldmatrix.sync.aligned.m8n8.x4.shared.b16 {%0,%1,%2,%3}, [%4];"
                 : "=r"(r0), "=r"(r1), "=r"(r2), "=r"(r3) : "r"(addr));
}
__device__ __forceinline__ void mma16816(float* c, const u32* a, const u32* b) {
    asm volatile("mma.sync.aligned.m16n8k16.row.col.f32.f16.f16.f32 "
                 "{%0,%1,%2,%3}, {%4,%5,%6,%7}, {%8,%9}, {%0,%1,%2,%3};"
                 : "+f"(c[0]), "+f"(c[1]), "+f"(c[2]), "+f"(c[3])
                 : "r"(a[0]), "r"(a[1]), "r"(a[2]), "r"(a[3]), "r"(b[0]), "r"(b[1]));
}
__device__ __forceinline__ void cp16(void* s, const void* g) {
    u32 a = smem_u32(s);
    asm volatile("cp.async.cg.shared.global [%0], [%1], 16;" :: "r"(a), "l"(g));
}
__device__ __forceinline__ void cp_commit() { asm volatile("cp.async.commit_group;"); }
__device__ __forceinline__ void cp_wait1()  { asm volatile("cp.async.wait_group 1;"); }
__device__ __forceinline__ void cp_wait0()  { asm volatile("cp.async.wait_group 0;"); }
union H8 { u16 s[8]; uint4 v; };

// ---------------------------------------------------------------- zero scratch
__global__ void k_zero() {
    int i = blockIdx.x * blockDim.x + threadIdx.x;
    if (i < NLEV * KCODES * DIM) g_sums[i] = 0.f;
    if (i < NLEV * KCODES)       g_counts[i] = 0.f;
    if (i < NLEV)                { g_loss_acc[i] = 0.0; g_c2max[i] = 0u; }
}

// ------------------------------------------------ codebook fp16-hi + ||C||^2 + max
__global__ void k_cbsplit(const float* __restrict__ codebooks) {
    const int row = blockIdx.x;            // NLEV*KCODES
    const int e0  = threadIdx.x * 8;       // 128 threads
    const float* src = codebooks + (size_t)row * DIM + e0;
    float4 v0 = *(const float4*)src;
    float4 v1 = *(const float4*)(src + 4);
    float xs[8] = {v0.x, v0.y, v0.z, v0.w, v1.x, v1.y, v1.z, v1.w};
    H8 ph;
    float s = 0.f;
#pragma unroll
    for (int i = 0; i < 8; i++) {
        s += xs[i] * xs[i];
        ph.s[i] = __half_as_ushort(__float2half_rn(xs[i]));
    }
    *(uint4*)(g_cbh + (size_t)row * DIM + e0) = ph.v;
#pragma unroll
    for (int o = 16; o; o >>= 1) s += __shfl_xor_sync(0xffffffffu, s, o);
    __shared__ float red[4];
    if ((threadIdx.x & 31) == 0) red[threadIdx.x >> 5] = s;
    __syncthreads();
    if (threadIdx.x == 0) {
        float c2 = red[0] + red[1] + red[2] + red[3];
        g_c2[row] = c2;
        atomicMax(&g_c2max[row >> 9], __float_as_uint(c2));   // c2 >= 0
    }
}

// ------------------------------------------------ fp16-hi of z_e (level-0 A operand)
__global__ void k_split0(const float* __restrict__ z_e) {
    const int tok = blockIdx.x * 2 + (threadIdx.x >> 7);
    const size_t off = (size_t)tok * DIM + (threadIdx.x & 127) * 8;
    float4 v0 = *(const float4*)(z_e + off);
    float4 v1 = *(const float4*)(z_e + off + 4);
    float xs[8] = {v0.x, v0.y, v0.z, v0.w, v1.x, v1.y, v1.z, v1.w};
    H8 ph;
#pragma unroll
    for (int i = 0; i < 8; i++) ph.s[i] = __half_as_ushort(__float2half_rn(xs[i]));
    *(uint4*)(g_ah + off) = ph.v;
}

// ---------------------------------------------------------------- phase 1: hh scores
// Block: 64 tokens x 512 codes (4 ct tiles of 128). 8 warps: mw=wid&1 (32-token
// slice), nw=wid>>1 (32-code slice). Warp tile 32x32. cp.async double-buffered
// 64-k chunks (wait_group 1 => chunk k+1 staging overlaps chunk k compute).
// score fp16 -> g_scoreh.
#define ASTRIDE 72
#define SA_ELE (64 * ASTRIDE)      // 4608 halves
#define SB_ELE (128 * ASTRIDE)     // 9216 halves
#define BUF_ELE (SA_ELE + SB_ELE)  // 13824 halves = 27648 B
#define SMEM_SCORE (2 * BUF_ELE * 2)   // 55296 B

__global__ void __launch_bounds__(256, 2) k_score(int level) {
    extern __shared__ __align__(16) u16 dsm[];

    const int tid = threadIdx.x, wid = tid >> 5, lane = tid & 31;
    const int mw = wid & 1, nw = wid >> 1;
    const int t0 = blockIdx.x * 64;

    const u16* bh = g_cbh + (size_t)level * KCODES * DIM;
    const float* c2p = g_c2 + level * KCODES;

    const int srow = tid >> 3, sg = tid & 7;

    // ldmatrix addressing
    const int aro = mw * 32 + (lane & 15);         // + mg*16
    const int aco = (lane >> 4) * 8;               // + k0
    const int matid = lane >> 3;
    const int selj = matid >> 1, selk = matid & 1;
    const int bro = nw * 32 + selj * 8 + (lane & 7);  // + jp*16
    const int bco = selk * 8;                          // + k0

    // stage chunk it = ct*16 + kc into buffer b
    auto stage = [&](int it, int b) {
        const int ct = it >> 4, d0 = (it & 15) * 64;
        u16* bufA = dsm + b * BUF_ELE;
        u16* bufB = bufA + SA_ELE;
#pragma unroll
        for (int i = 0; i < 2; i++) {
            int r = srow + i * 32;
            cp16(&bufA[r * ASTRIDE + sg * 8], g_ah + (size_t)(t0 + r) * DIM + d0 + sg * 8);
        }
#pragma unroll
        for (int i = 0; i < 4; i++) {
            int r = srow + i * 32;
            cp16(&bufB[r * ASTRIDE + sg * 8], bh + (size_t)(ct * 128 + r) * DIM + d0 + sg * 8);
        }
        cp_commit();
    };

    float c[2][4][4];
#pragma unroll
    for (int mg = 0; mg < 2; mg++)
#pragma unroll
        for (int ng = 0; ng < 4; ng++)
#pragma unroll
            for (int q = 0; q < 4; q++) c[mg][ng][q] = 0.f;

    stage(0, 0);

    for (int it = 0; it < 64; it++) {
        const int b = it & 1;
        if (it + 1 < 64) { stage(it + 1, b ^ 1); cp_wait1(); } else { cp_wait0(); }
        __syncthreads();                        // buffer b ready for all warps

        const u32 aA = smem_u32(dsm + b * BUF_ELE);
        const u32 aB = smem_u32(dsm + b * BUF_ELE + SA_ELE);
#pragma unroll
        for (int kk = 0; kk < 4; kk++) {
            const int k0 = kk * 16;
            u32 Am[2][4];
#pragma unroll
            for (int mg = 0; mg < 2; mg++)
                ldsm4(Am[mg][0], Am[mg][1], Am[mg][2], Am[mg][3],
                      aA + (u32)(((aro + mg * 16) * ASTRIDE + aco + k0) * 2));
#pragma unroll
            for (int jp = 0; jp < 2; jp++) {
                u32 Bf[4];
                ldsm4(Bf[0], Bf[1], Bf[2], Bf[3],
                      aB + (u32)(((bro + jp * 16) * ASTRIDE + bco + k0) * 2));
#pragma unroll
                for (int mg = 0; mg < 2; mg++) {
                    mma16816(c[mg][2 * jp],     Am[mg], &Bf[0]);
                    mma16816(c[mg][2 * jp + 1], Am[mg], &Bf[2]);
                }
            }
        }

        if ((it & 15) == 15) {
            // epilogue for this 128-code tile: fp16 scores
            const int ct = it >> 4;
#pragma unroll
            for (int mg = 0; mg < 2; mg++) {
                const int row0 = t0 + mw * 32 + mg * 16 + (lane >> 2);
#pragma unroll
                for (int ng = 0; ng < 4; ng++) {
                    const int id = ct * 128 + nw * 32 + ng * 8 + 2 * (lane & 3);
                    const float c2a = __ldg(c2p + id);
                    const float c2b = __ldg(c2p + id + 1);
                    __half2 pa = __floats2half2_rn(c2a - 2.f * c[mg][ng][0], c2b - 2.f * c[mg][ng][1]);
                    __half2 pb = __floats2half2_rn(c2a - 2.f * c[mg][ng][2], c2b - 2.f * c[mg][ng][3]);
                    *(u32*)(g_scoreh + (size_t)row0 * KCODES + id)       = *(u32*)&pa;
                    *(u32*)(g_scoreh + (size_t)(row0 + 8) * KCODES + id) = *(u32*)&pb;
#pragma unroll
                    for (int q = 0; q < 4; q++) c[mg][ng][q] = 0.f;
                }
            }
        }
        __syncthreads();                        // all reads of buffer b done
    }
}

// ---------------------------------------------------------------- phase 2: pick + update (fused)
// One warp per token: hh-min over fp16 scores, exact fp32 rescore of candidates
// within a provable margin, then full EMA/residual update.
// z_q is NOT accumulated: out_zq = z_e - residual_final, written at level 2 only.
__global__ void __launch_bounds__(256) k_pick(int level,
                                              const float* __restrict__ z_e,
                                              const float* __restrict__ codebooks,
                                              float* __restrict__ out_zq,
                                              float* __restrict__ out_idx) {
    const int wid = threadIdx.x >> 5, lane = threadIdx.x & 31;
    const int tok = blockIdx.x * 8 + wid;
    const float* c2p = g_c2 + level * KCODES;
    const float* cbl = codebooks + (size_t)level * KCODES * DIM;
    const u16* srow = g_scoreh + (size_t)tok * KCODES;

    // fp16 scores: lane covers codes {lane*4 + i*128 + (0..3)}
    float s[16];
    float mv = 3.4e38f; int mi = 0;
#pragma unroll
    for (int i = 0; i < 4; i++) {
        uint2 pv = *(const uint2*)(srow + lane * 4 + i * 128);
        float2 f0 = __half22float2(*(__half2*)&pv.x);
        float2 f1 = __half22float2(*(__half2*)&pv.y);
        const int c0 = lane * 4 + i * 128;
        s[i * 4 + 0] = f0.x; s[i * 4 + 1] = f0.y; s[i * 4 + 2] = f1.x; s[i * 4 + 3] = f1.y;
        if (f0.x < mv || (f0.x == mv && c0     < mi)) { mv = f0.x; mi = c0; }
        if (f0.y < mv || (f0.y == mv && c0 + 1 < mi)) { mv = f0.y; mi = c0 + 1; }
        if (f1.x < mv || (f1.x == mv && c0 + 2 < mi)) { mv = f1.x; mi = c0 + 2; }
        if (f1.y < mv || (f1.y == mv && c0 + 3 < mi)) { mv = f1.y; mi = c0 + 3; }
    }
#pragma unroll
    for (int o = 16; o; o >>= 1) {
        float ov = __shfl_xor_sync(0xffffffffu, mv, o);
        int   oi = __shfl_xor_sync(0xffffffffu, mi, o);
        if (ov < mv || (ov == mv && oi < mi)) { mv = ov; mi = oi; }
    }

    // residual: lane holds dims [lane*32, lane*32+32)
    const float* rin = (level ? g_residual : z_e) + (size_t)tok * DIM + lane * 32;
    float4 r4[8];
    float r2 = 0.f;
#pragma unroll
    for (int v = 0; v < 8; v++) {
        r4[v] = *(const float4*)(rin + v * 4);
        r2 += r4[v].x * r4[v].x + r4[v].y * r4[v].y + r4[v].z * r4[v].z + r4[v].w * r4[v].w;
    }
#pragma unroll
    for (int o = 16; o; o >>= 1) r2 += __shfl_xor_sync(0xffffffffu, r2, o);

    const float c2mx = __uint_as_float(g_c2max[level]);
    const float cmax = sqrtf(c2mx);
    const float rn   = sqrtf(r2);
    const float smax = c2mx + 2.f * rn * cmax;               // bound on |score|
    const float thr  = mv + 0.0039f * rn * cmax + 0.001f * smax + 0.5f;

    // exact rescore of candidates
    float bestv = 3.4e38f; int besti = 0;
#pragma unroll
    for (int i = 0; i < 16; i++) {
        const int cid_l = lane * 4 + (i >> 2) * 128 + (i & 3);
        u32 m = __ballot_sync(0xffffffffu, s[i] <= thr);
        while (m) {
            const int src = __ffs(m) - 1; m &= m - 1;
            const int cid = __shfl_sync(0xffffffffu, cid_l, src);
            const float* crow = cbl + (size_t)cid * DIM + lane * 32;
            float dot = 0.f;
#pragma unroll
            for (int v = 0; v < 8; v++) {
                float4 q = __ldg((const float4*)(crow + v * 4));
                dot += r4[v].x * q.x + r4[v].y * q.y + r4[v].z * q.z + r4[v].w * q.w;
            }
#pragma unroll
            for (int o = 16; o; o >>= 1) dot += __shfl_xor_sync(0xffffffffu, dot, o);
            const float sc = __ldg(c2p + cid) - 2.f * dot;
            if (sc < bestv || (sc == bestv && cid < besti)) { bestv = sc; besti = cid; }
        }
    }

    // ---- fused update ----
    const float* qrow = cbl + (size_t)besti * DIM + lane * 32;
    float* sums = g_sums + ((size_t)(level * KCODES + besti)) * DIM + lane * 32;
    float* rout = g_residual + (size_t)tok * DIM + lane * 32;
    const float* zrow = z_e + (size_t)tok * DIM + lane * 32;
    float* zo = out_zq + (size_t)tok * DIM + lane * 32;

    float ls = 0.f;
    H8 ph[4];
#pragma unroll
    for (int v = 0; v < 8; v++) {
        float4 q = __ldg((const float4*)(qrow + v * 4));
        float4 rq = make_float4(r4[v].x - q.x, r4[v].y - q.y, r4[v].z - q.z, r4[v].w - q.w);
        ls += rq.x * rq.x + rq.y * rq.y + rq.z * rq.z + rq.w * rq.w;
        if (level < 2) {
            *(float4*)(rout + v * 4) = rq;
            const int g = v >> 1, e = (v & 1) * 4;
            ph[g].s[e + 0] = __half_as_ushort(__float2half_rn(rq.x));
            ph[g].s[e + 1] = __half_as_ushort(__float2half_rn(rq.y));
            ph[g].s[e + 2] = __half_as_ushort(__float2half_rn(rq.z));
            ph[g].s[e + 3] = __half_as_ushort(__float2half_rn(rq.w));
        } else {
            float4 ze = __ldg((const float4*)(zrow + v * 4));
            *(float4*)(zo + v * 4) = make_float4(ze.x - rq.x, ze.y - rq.y, ze.z - rq.z, ze.w - rq.w);
        }
        red4(sums + v * 4, r4[v]);
    }
    if (level < 2) {
        u16* ao = g_ah + (size_t)tok * DIM + lane * 32;
#pragma unroll
        for (int g = 0; g < 4; g++) *(uint4*)(ao + g * 8) = ph[g].v;
    }
    if (lane == 0) {
        atomicAdd(g_counts + level * KCODES + besti, 1.0f);
        out_idx[(size_t)level * NTOK + tok] = (float)besti;
    }

    // block loss reduction -> one double atomic
#pragma unroll
    for (int o = 16; o; o >>= 1) ls += __shfl_xor_sync(0xffffffffu, ls, o);
    __shared__ float red[8];
    if (lane == 0) red[wid] = ls;
    __syncthreads();
    if (threadIdx.x < 8) {
        float v = red[threadIdx.x];
#pragma unroll
        for (int o = 4; o; o >>= 1) v += __shfl_xor_sync(0xffu, v, o);
        if (threadIdx.x == 0) atomicAdd(&g_loss_acc[level], (double)v);
    }
}

// ---------------------------------------------------------------- cs + n
__global__ void k_csn(const float* __restrict__ ema_cluster) {
    const int l = blockIdx.x;
    const int k = threadIdx.x;   // 512 threads
    float cs = DECAY * ema_cluster[l * KCODES + k] + OMD * g_counts[l * KCODES + k];
    g_cs[l * KCODES + k] = cs;
    float s = cs;
#pragma unroll
    for (int o = 16; o; o >>= 1) s += __shfl_xor_sync(0xffffffffu, s, o);
    __shared__ float red[16];
    const int warp = threadIdx.x >> 5, lane = threadIdx.x & 31;
    if (lane == 0) red[warp] = s;
    __syncthreads();
    if (threadIdx.x < 16) {
        float v = red[threadIdx.x];
#pragma unroll
        for (int o = 8; o; o >>= 1) v += __shfl_xor_sync(0xffffu, v, o);
        if (threadIdx.x == 0) g_n[l] = v;
    }
}

// ---------------------------------------------------------------- new codebooks + loss
__global__ void k_cb(const float* __restrict__ ema_w,
                     float* __restrict__ out_cb,
                     float* __restrict__ out_loss) {
    const int i = blockIdx.x * blockDim.x + threadIdx.x;
    if (i == 0) {
        double L = (0.25 * g_loss_acc[0] + 0.5 * g_loss_acc[1] + 1.0 * g_loss_acc[2])
                   * (1.0 / ((double)NTOK * (double)DIM));
        *out_loss = (float)L;
    }
    if (i >= NLEV * KCODES * DIM) return;
    const int row = i >> 10;
    const int l   = row >> 9;
    float w  = DECAY * ema_w[i] + OMD * g_sums[i];
    float cs = g_cs[row];
    float n  = g_n[l];
    float csn = (cs + EPSV) / (n + 0.00512f) * n;   // K*EPS = 512e-5
    out_cb[i] = w / csn;
}

// ---------------------------------------------------------------- launch
extern "C" void kernel_launch(void* const* d_in, const int* in_sizes, int n_in,
                              void* d_out, int out_size) {
    const float* z_e         = (const float*)d_in[0];
    const float* codebooks   = (const float*)d_in[1];
    const float* ema_cluster = (const float*)d_in[2];
    const float* ema_w       = (const float*)d_in[3];
    float* out = (float*)d_out;

    const size_t ZQ = (size_t)NTOK * DIM;
    float* out_zq   = out;
    float* out_loss = out + ZQ;
    float* out_idx  = out + ZQ + 1;
    float* out_cb   = out + ZQ + 1 + (size_t)NLEV * NTOK;

    cudaFuncSetAttribute(k_score, cudaFuncAttributeMaxDynamicSharedMemorySize, SMEM_SCORE);

    k_zero<<<(NLEV * KCODES * DIM + 255) / 256, 256>>>();
    k_cbsplit<<<NLEV * KCODES, 128>>>(codebooks);
    k_split0<<<NTOK / 2, 256>>>(z_e);
    for (int l = 0; l < NLEV; l++) {
        k_score<<<NTOK / 64, 256, SMEM_SCORE>>>(l);
        k_pick<<<NTOK / 8, 256>>>(l, z_e, codebooks, out_zq, out_idx);
    }
    k_csn<<<NLEV, 512>>>(ema_cluster);
    k_cb<<<(NLEV * KCODES * DIM + 255) / 256, 256>>>(ema_w, out_cb, out_loss);
}

// round 13
// speedup vs baseline: 4.7065x; 1.0683x over previous
#include <cuda_runtime.h>
#include <cuda_fp16.h>
#include <cstdint>

#define NLEV   3
#define KCODES 512
#define DIM    1024
#define NTOK   65536           // 16 * 4096
#define DECAY  0.99f
#define OMD    0.01f
#define EPSV   1e-5f

typedef unsigned long long ull;
typedef unsigned int       u32;
typedef unsigned short     u16;

// ---- scratch (__device__ globals: the sanctioned no-alloc path) ----
static __device__ __align__(16) u16   g_ah[(size_t)NTOK * DIM];         // 134 MB fp16 hi(resid)
static __device__ __align__(16) u16   g_al[(size_t)NTOK * DIM];         // 134 MB fp16 lo(resid)
static __device__ __align__(16) u16   g_cbh[NLEV * KCODES * DIM];       // 3 MB fp16 hi
static __device__ __align__(16) u16   g_scoreh[(size_t)NTOK * KCODES];  // 67 MB fp16 scores
static __device__ __align__(16) float g_sums[NLEV * KCODES * DIM];      // 6 MB
static __device__ float  g_counts[NLEV * KCODES];
static __device__ float  g_c2[NLEV * KCODES];
static __device__ u32    g_c2max[NLEV];
static __device__ float  g_cs[NLEV * KCODES];
static __device__ float  g_n[NLEV];
static __device__ double g_loss_acc[NLEV];

__device__ __forceinline__ u32 smem_u32(const void* p) {
    u32 a;
    asm("{ .reg .u64 t; cvta.to.shared.u64 t, %1; cvt.u32.u64 %0, t; }" : "=r"(a) : "l"(p));
    return a;
}
__device__ __forceinline__ void red4(float* p, float4 v) {
    asm volatile("red.global.add.v4.f32 [%0], {%1,%2,%3,%4};"
                 :: "l"(p), "f"(v.x), "f"(v.y), "f"(v.z), "f"(v.w) : "memory");
}
__device__ __forceinline__ void ldsm4(u32& r0, u32& r1, u32& r2, u32& r3, u32 addr) {
    asm volatile("ldmatrix.sync.aligned.m8n8.x4.shared.b16 {%0,%1,%2,%3}, [%4];"
                 : "=r"(r0), "=r"(r1), "=r"(r2), "=r"(r3) : "r"(addr));
}
__device__ __forceinline__ void mma16816(float* c, const u32* a, const u32* b) {
    asm volatile("mma.sync.aligned.m16n8k16.row.col.f32.f16.f16.f32 "
                 "{%0,%1,%2,%3}, {%4,%5,%6,%7}, {%8,%9}, {%0,%1,%2,%3};"
                 : "+f"(c[0]), "+f"(c[1]), "+f"(c[2]), "+f"(c[3])
                 : "r"(a[0]), "r"(a[1]), "r"(a[2]), "r"(a[3]), "r"(b[0]), "r"(b[1]));
}
__device__ __forceinline__ void cp16(void* s, const void* g) {
    u32 a = smem_u32(s);
    asm volatile("cp.async.cg.shared.global [%0], [%1], 16;" :: "r"(a), "l"(g));
}
__device__ __forceinline__ void cp_commit() { asm volatile("cp.async.commit_group;"); }
__device__ __forceinline__ void cp_wait1()  { asm volatile("cp.async.wait_group 1;"); }
__device__ __forceinline__ void cp_wait0()  { asm volatile("cp.async.wait_group 0;"); }
// 2-way fp16 split: x = hi + lo exactly to ~2^-22
__device__ __forceinline__ void split2(float x, u16& h, u16& l) {
    __half hh = __float2half_rn(x);
    __half ll = __float2half_rn(x - __half2float(hh));
    h = __half_as_ushort(hh); l = __half_as_ushort(ll);
}
union H8 { u16 s[8]; uint4 v; };

// ---------------------------------------------------------------- zero scratch
__global__ void k_zero() {
    int i = blockIdx.x * blockDim.x + threadIdx.x;
    if (i < NLEV * KCODES * DIM) g_sums[i] = 0.f;
    if (i < NLEV * KCODES)       g_counts[i] = 0.f;
    if (i < NLEV)                { g_loss_acc[i] = 0.0; g_c2max[i] = 0u; }
}

// ------------------------------------------------ codebook fp16-hi + ||C||^2 + max
__global__ void k_cbsplit(const float* __restrict__ codebooks) {
    const int row = blockIdx.x;            // NLEV*KCODES
    const int e0  = threadIdx.x * 8;       // 128 threads
    const float* src = codebooks + (size_t)row * DIM + e0;
    float4 v0 = *(const float4*)src;
    float4 v1 = *(const float4*)(src + 4);
    float xs[8] = {v0.x, v0.y, v0.z, v0.w, v1.x, v1.y, v1.z, v1.w};
    H8 ph;
    float s = 0.f;
#pragma unroll
    for (int i = 0; i < 8; i++) {
        s += xs[i] * xs[i];
        ph.s[i] = __half_as_ushort(__float2half_rn(xs[i]));
    }
    *(uint4*)(g_cbh + (size_t)row * DIM + e0) = ph.v;
#pragma unroll
    for (int o = 16; o; o >>= 1) s += __shfl_xor_sync(0xffffffffu, s, o);
    __shared__ float red[4];
    if ((threadIdx.x & 31) == 0) red[threadIdx.x >> 5] = s;
    __syncthreads();
    if (threadIdx.x == 0) {
        float c2 = red[0] + red[1] + red[2] + red[3];
        g_c2[row] = c2;
        atomicMax(&g_c2max[row >> 9], __float_as_uint(c2));   // c2 >= 0
    }
}

// ---------------------------------------------------------------- phase 1: hh scores
// Block: 64 tokens x 512 codes (4 ct tiles of 128). 8 warps: mw=wid&1 (32-token
// slice), nw=wid>>1 (32-code slice). cp.async double-buffered 64-k chunks.
// Level 0 stages A from z_e (f32) with LDG+cvt+STS; levels 1-2 from g_ah.
#define ASTRIDE 72
#define SA_ELE (64 * ASTRIDE)      // 4608 halves
#define SB_ELE (128 * ASTRIDE)     // 9216 halves
#define BUF_ELE (SA_ELE + SB_ELE)  // 13824 halves = 27648 B
#define SMEM_SCORE (2 * BUF_ELE * 2)   // 55296 B

__global__ void __launch_bounds__(256, 2) k_score(int level, const float* __restrict__ z_e) {
    extern __shared__ __align__(16) u16 dsm[];

    const int tid = threadIdx.x, wid = tid >> 5, lane = tid & 31;
    const int mw = wid & 1, nw = wid >> 1;
    const int t0 = blockIdx.x * 64;
    const bool lvl0 = (level == 0);

    const u16* bh = g_cbh + (size_t)level * KCODES * DIM;
    const float* c2p = g_c2 + level * KCODES;

    const int srow = tid >> 3, sg = tid & 7;

    // ldmatrix addressing
    const int aro = mw * 32 + (lane & 15);         // + mg*16
    const int aco = (lane >> 4) * 8;               // + k0
    const int matid = lane >> 3;
    const int selj = matid >> 1, selk = matid & 1;
    const int bro = nw * 32 + selj * 8 + (lane & 7);  // + jp*16
    const int bco = selk * 8;                          // + k0

    // stage chunk it = ct*16 + kc into buffer b
    auto stage = [&](int it, int b) {
        const int ct = it >> 4, d0 = (it & 15) * 64;
        u16* bufA = dsm + b * BUF_ELE;
        u16* bufB = bufA + SA_ELE;
        if (lvl0) {
#pragma unroll
            for (int i = 0; i < 2; i++) {
                int r = srow + i * 32;
                const float* src = z_e + (size_t)(t0 + r) * DIM + d0 + sg * 8;
                float4 v0 = __ldg((const float4*)src);
                float4 v1 = __ldg((const float4*)(src + 4));
                H8 ph;
                ph.s[0] = __half_as_ushort(__float2half_rn(v0.x));
                ph.s[1] = __half_as_ushort(__float2half_rn(v0.y));
                ph.s[2] = __half_as_ushort(__float2half_rn(v0.z));
                ph.s[3] = __half_as_ushort(__float2half_rn(v0.w));
                ph.s[4] = __half_as_ushort(__float2half_rn(v1.x));
                ph.s[5] = __half_as_ushort(__float2half_rn(v1.y));
                ph.s[6] = __half_as_ushort(__float2half_rn(v1.z));
                ph.s[7] = __half_as_ushort(__float2half_rn(v1.w));
                *(uint4*)&bufA[r * ASTRIDE + sg * 8] = ph.v;
            }
        } else {
#pragma unroll
            for (int i = 0; i < 2; i++) {
                int r = srow + i * 32;
                cp16(&bufA[r * ASTRIDE + sg * 8], g_ah + (size_t)(t0 + r) * DIM + d0 + sg * 8);
            }
        }
#pragma unroll
        for (int i = 0; i < 4; i++) {
            int r = srow + i * 32;
            cp16(&bufB[r * ASTRIDE + sg * 8], bh + (size_t)(ct * 128 + r) * DIM + d0 + sg * 8);
        }
        cp_commit();
    };

    float c[2][4][4];
#pragma unroll
    for (int mg = 0; mg < 2; mg++)
#pragma unroll
        for (int ng = 0; ng < 4; ng++)
#pragma unroll
            for (int q = 0; q < 4; q++) c[mg][ng][q] = 0.f;

    stage(0, 0);

    for (int it = 0; it < 64; it++) {
        const int b = it & 1;
        if (it + 1 < 64) { stage(it + 1, b ^ 1); cp_wait1(); } else { cp_wait0(); }
        __syncthreads();                        // buffer b ready for all warps

        const u32 aA = smem_u32(dsm + b * BUF_ELE);
        const u32 aB = smem_u32(dsm + b * BUF_ELE + SA_ELE);
#pragma unroll
        for (int kk = 0; kk < 4; kk++) {
            const int k0 = kk * 16;
            u32 Am[2][4];
#pragma unroll
            for (int mg = 0; mg < 2; mg++)
                ldsm4(Am[mg][0], Am[mg][1], Am[mg][2], Am[mg][3],
                      aA + (u32)(((aro + mg * 16) * ASTRIDE + aco + k0) * 2));
#pragma unroll
            for (int jp = 0; jp < 2; jp++) {
                u32 Bf[4];
                ldsm4(Bf[0], Bf[1], Bf[2], Bf[3],
                      aB + (u32)(((bro + jp * 16) * ASTRIDE + bco + k0) * 2));
#pragma unroll
                for (int mg = 0; mg < 2; mg++) {
                    mma16816(c[mg][2 * jp],     Am[mg], &Bf[0]);
                    mma16816(c[mg][2 * jp + 1], Am[mg], &Bf[2]);
                }
            }
        }

        if ((it & 15) == 15) {
            // epilogue for this 128-code tile: fp16 scores
            const int ct = it >> 4;
#pragma unroll
            for (int mg = 0; mg < 2; mg++) {
                const int row0 = t0 + mw * 32 + mg * 16 + (lane >> 2);
#pragma unroll
                for (int ng = 0; ng < 4; ng++) {
                    const int id = ct * 128 + nw * 32 + ng * 8 + 2 * (lane & 3);
                    const float c2a = __ldg(c2p + id);
                    const float c2b = __ldg(c2p + id + 1);
                    __half2 pa = __floats2half2_rn(c2a - 2.f * c[mg][ng][0], c2b - 2.f * c[mg][ng][1]);
                    __half2 pb = __floats2half2_rn(c2a - 2.f * c[mg][ng][2], c2b - 2.f * c[mg][ng][3]);
                    *(u32*)(g_scoreh + (size_t)row0 * KCODES + id)       = *(u32*)&pa;
                    *(u32*)(g_scoreh + (size_t)(row0 + 8) * KCODES + id) = *(u32*)&pb;
#pragma unroll
                    for (int q = 0; q < 4; q++) c[mg][ng][q] = 0.f;
                }
            }
        }
        __syncthreads();                        // all reads of buffer b done
    }
}

// ---------------------------------------------------------------- phase 2: pick + update (fused)
// One warp per token: hh-min over fp16 scores, exact fp32 rescore of candidates
// within a provable margin, then full EMA/residual update.
// Residual lives as fp16 hi+lo pair (g_ah+g_al); level-0 residual is z_e itself.
// out_zq = z_e - residual_final, written at level 2 only.
__global__ void __launch_bounds__(256) k_pick(int level,
                                              const float* __restrict__ z_e,
                                              const float* __restrict__ codebooks,
                                              float* __restrict__ out_zq,
                                              float* __restrict__ out_idx) {
    const int wid = threadIdx.x >> 5, lane = threadIdx.x & 31;
    const int tok = blockIdx.x * 8 + wid;
    const float* c2p = g_c2 + level * KCODES;
    const float* cbl = codebooks + (size_t)level * KCODES * DIM;
    const u16* srow = g_scoreh + (size_t)tok * KCODES;

    // fp16 scores: lane covers codes {lane*4 + i*128 + (0..3)}
    float s[16];
    float mv = 3.4e38f; int mi = 0;
#pragma unroll
    for (int i = 0; i < 4; i++) {
        uint2 pv = *(const uint2*)(srow + lane * 4 + i * 128);
        float2 f0 = __half22float2(*(__half2*)&pv.x);
        float2 f1 = __half22float2(*(__half2*)&pv.y);
        const int c0 = lane * 4 + i * 128;
        s[i * 4 + 0] = f0.x; s[i * 4 + 1] = f0.y; s[i * 4 + 2] = f1.x; s[i * 4 + 3] = f1.y;
        if (f0.x < mv || (f0.x == mv && c0     < mi)) { mv = f0.x; mi = c0; }
        if (f0.y < mv || (f0.y == mv && c0 + 1 < mi)) { mv = f0.y; mi = c0 + 1; }
        if (f1.x < mv || (f1.x == mv && c0 + 2 < mi)) { mv = f1.x; mi = c0 + 2; }
        if (f1.y < mv || (f1.y == mv && c0 + 3 < mi)) { mv = f1.y; mi = c0 + 3; }
    }
#pragma unroll
    for (int o = 16; o; o >>= 1) {
        float ov = __shfl_xor_sync(0xffffffffu, mv, o);
        int   oi = __shfl_xor_sync(0xffffffffu, mi, o);
        if (ov < mv || (ov == mv && oi < mi)) { mv = ov; mi = oi; }
    }

    // residual: lane holds dims [lane*32, lane*32+32)
    float4 r4[8];
    float r2 = 0.f;
    if (level == 0) {
        const float* rin = z_e + (size_t)tok * DIM + lane * 32;
#pragma unroll
        for (int v = 0; v < 8; v++) r4[v] = *(const float4*)(rin + v * 4);
    } else {
        const u16* ap = g_ah + (size_t)tok * DIM + lane * 32;
        const u16* lp = g_al + (size_t)tok * DIM + lane * 32;
#pragma unroll
        for (int g = 0; g < 4; g++) {
            uint4 hv = *(const uint4*)(ap + g * 8);
            uint4 lv = *(const uint4*)(lp + g * 8);
            const __half2* hh = (const __half2*)&hv;
            const __half2* ll = (const __half2*)&lv;
            float2 a0 = __half22float2(hh[0]), b0 = __half22float2(ll[0]);
            float2 a1 = __half22float2(hh[1]), b1 = __half22float2(ll[1]);
            float2 a2 = __half22float2(hh[2]), b2 = __half22float2(ll[2]);
            float2 a3 = __half22float2(hh[3]), b3 = __half22float2(ll[3]);
            r4[2 * g]     = make_float4(a0.x + b0.x, a0.y + b0.y, a1.x + b1.x, a1.y + b1.y);
            r4[2 * g + 1] = make_float4(a2.x + b2.x, a2.y + b2.y, a3.x + b3.x, a3.y + b3.y);
        }
    }
#pragma unroll
    for (int v = 0; v < 8; v++)
        r2 += r4[v].x * r4[v].x + r4[v].y * r4[v].y + r4[v].z * r4[v].z + r4[v].w * r4[v].w;
#pragma unroll
    for (int o = 16; o; o >>= 1) r2 += __shfl_xor_sync(0xffffffffu, r2, o);

    const float c2mx = __uint_as_float(g_c2max[level]);
    const float cmax = sqrtf(c2mx);
    const float rn   = sqrtf(r2);
    const float smax = c2mx + 2.f * rn * cmax;               // bound on |score|
    const float thr  = mv + 0.0039f * rn * cmax + 0.001f * smax + 0.5f;

    // exact rescore of candidates
    float bestv = 3.4e38f; int besti = 0;
#pragma unroll
    for (int i = 0; i < 16; i++) {
        const int cid_l = lane * 4 + (i >> 2) * 128 + (i & 3);
        u32 m = __ballot_sync(0xffffffffu, s[i] <= thr);
        while (m) {
            const int src = __ffs(m) - 1; m &= m - 1;
            const int cid = __shfl_sync(0xffffffffu, cid_l, src);
            const float* crow = cbl + (size_t)cid * DIM + lane * 32;
            float dot = 0.f;
#pragma unroll
            for (int v = 0; v < 8; v++) {
                float4 q = __ldg((const float4*)(crow + v * 4));
                dot += r4[v].x * q.x + r4[v].y * q.y + r4[v].z * q.z + r4[v].w * q.w;
            }
#pragma unroll
            for (int o = 16; o; o >>= 1) dot += __shfl_xor_sync(0xffffffffu, dot, o);
            const float sc = __ldg(c2p + cid) - 2.f * dot;
            if (sc < bestv || (sc == bestv && cid < besti)) { bestv = sc; besti = cid; }
        }
    }

    // ---- fused update ----
    const float* qrow = cbl + (size_t)besti * DIM + lane * 32;
    float* sums = g_sums + ((size_t)(level * KCODES + besti)) * DIM + lane * 32;
    const float* zrow = z_e + (size_t)tok * DIM + lane * 32;
    float* zo = out_zq + (size_t)tok * DIM + lane * 32;

    float ls = 0.f;
    H8 ph[4], pl[4];
#pragma unroll
    for (int v = 0; v < 8; v++) {
        float4 q = __ldg((const float4*)(qrow + v * 4));
        float4 rq = make_float4(r4[v].x - q.x, r4[v].y - q.y, r4[v].z - q.z, r4[v].w - q.w);
        ls += rq.x * rq.x + rq.y * rq.y + rq.z * rq.z + rq.w * rq.w;
        if (level < 2) {
            const int g = v >> 1, e = (v & 1) * 4;
            split2(rq.x, ph[g].s[e + 0], pl[g].s[e + 0]);
            split2(rq.y, ph[g].s[e + 1], pl[g].s[e + 1]);
            split2(rq.z, ph[g].s[e + 2], pl[g].s[e + 2]);
            split2(rq.w, ph[g].s[e + 3], pl[g].s[e + 3]);
        } else {
            float4 ze = __ldg((const float4*)(zrow + v * 4));
            *(float4*)(zo + v * 4) = make_float4(ze.x - rq.x, ze.y - rq.y, ze.z - rq.z, ze.w - rq.w);
        }
        red4(sums + v * 4, r4[v]);
    }
    if (level < 2) {
        u16* ao = g_ah + (size_t)tok * DIM + lane * 32;
        u16* lo = g_al + (size_t)tok * DIM + lane * 32;
#pragma unroll
        for (int g = 0; g < 4; g++) {
            *(uint4*)(ao + g * 8) = ph[g].v;
            *(uint4*)(lo + g * 8) = pl[g].v;
        }
    }
    if (lane == 0) {
        atomicAdd(g_counts + level * KCODES + besti, 1.0f);
        out_idx[(size_t)level * NTOK + tok] = (float)besti;
    }

    // block loss reduction -> one double atomic
#pragma unroll
    for (int o = 16; o; o >>= 1) ls += __shfl_xor_sync(0xffffffffu, ls, o);
    __shared__ float red[8];
    if (lane == 0) red[wid] = ls;
    __syncthreads();
    if (threadIdx.x < 8) {
        float v = red[threadIdx.x];
#pragma unroll
        for (int o = 4; o; o >>= 1) v += __shfl_xor_sync(0xffu, v, o);
        if (threadIdx.x == 0) atomicAdd(&g_loss_acc[level], (double)v);
    }
}

// ---------------------------------------------------------------- cs + n
__global__ void k_csn(const float* __restrict__ ema_cluster) {
    const int l = blockIdx.x;
    const int k = threadIdx.x;   // 512 threads
    float cs = DECAY * ema_cluster[l * KCODES + k] + OMD * g_counts[l * KCODES + k];
    g_cs[l * KCODES + k] = cs;
    float s = cs;
#pragma unroll
    for (int o = 16; o; o >>= 1) s += __shfl_xor_sync(0xffffffffu, s, o);
    __shared__ float red[16];
    const int warp = threadIdx.x >> 5, lane = threadIdx.x & 31;
    if (lane == 0) red[warp] = s;
    __syncthreads();
    if (threadIdx.x < 16) {
        float v = red[threadIdx.x];
#pragma unroll
        for (int o = 8; o; o >>= 1) v += __shfl_xor_sync(0xffffu, v, o);
        if (threadIdx.x == 0) g_n[l] = v;
    }
}

// ---------------------------------------------------------------- new codebooks + loss
__global__ void k_cb(const float* __restrict__ ema_w,
                     float* __restrict__ out_cb,
                     float* __restrict__ out_loss) {
    const int i = blockIdx.x * blockDim.x + threadIdx.x;
    if (i == 0) {
        double L = (0.25 * g_loss_acc[0] + 0.5 * g_loss_acc[1] + 1.0 * g_loss_acc[2])
                   * (1.0 / ((double)NTOK * (double)DIM));
        *out_loss = (float)L;
    }
    if (i >= NLEV * KCODES * DIM) return;
    const int row = i >> 10;
    const int l   = row >> 9;
    float w  = DECAY * ema_w[i] + OMD * g_sums[i];
    float cs = g_cs[row];
    float n  = g_n[l];
    float csn = (cs + EPSV) / (n + 0.00512f) * n;   // K*EPS = 512e-5
    out_cb[i] = w / csn;
}

// ---------------------------------------------------------------- launch
extern "C" void kernel_launch(void* const* d_in, const int* in_sizes, int n_in,
                              void* d_out, int out_size) {
    const float* z_e         = (const float*)d_in[0];
    const float* codebooks   = (const float*)d_in[1];
    const float* ema_cluster = (const float*)d_in[2];
    const float* ema_w       = (const float*)d_in[3];
    float* out = (float*)d_out;

    const size_t ZQ = (size_t)NTOK * DIM;
    float* out_zq   = out;
    float* out_loss = out + ZQ;
    float* out_idx  = out + ZQ + 1;
    float* out_cb   = out + ZQ + 1 + (size_t)NLEV * NTOK;

    cudaFuncSetAttribute(k_score, cudaFuncAttributeMaxDynamicSharedMemorySize, SMEM_SCORE);

    k_zero<<<(NLEV * KCODES * DIM + 255) / 256, 256>>>();
    k_cbsplit<<<NLEV * KCODES, 128>>>(codebooks);
    for (int l = 0; l < NLEV; l++) {
        k_score<<<NTOK / 64, 256, SMEM_SCORE>>>(l, z_e);
        k_pick<<<NTOK / 8, 256>>>(l, z_e, codebooks, out_zq, out_idx);
    }
    k_csn<<<NLEV, 512>>>(ema_cluster);
    k_cb<<<(NLEV * KCODES * DIM + 255) / 256, 256>>>(ema_w, out_cb, out_loss);
}